// round 10
// baseline (speedup 1.0000x reference)
#include <cuda_runtime.h>
#include <cstdint>

typedef unsigned long long u64;

__device__ __forceinline__ u64 pk(float x) {
    u64 r; asm("mov.b64 %0, {%1, %1};" : "=l"(r) : "f"(x)); return r;
}
__device__ __forceinline__ u64 pk2(float x, float y) {
    u64 r; asm("mov.b64 %0, {%1, %2};" : "=l"(r) : "f"(x), "f"(y)); return r;
}
__device__ __forceinline__ void fma2(u64& d, u64 a, u64 b) {
    asm("fma.rn.f32x2 %0, %1, %2, %0;" : "+l"(d) : "l"(a), "l"(b));
}
__device__ __forceinline__ float2 upk(u64 v) {
    float2 r; asm("mov.b64 {%0, %1}, %2;" : "=f"(r.x), "=f"(r.y) : "l"(v)); return r;
}

// Problem constants
#define BB   2048
#define LL   128

// Output layout (concatenated, float32)
#define OFF_PUZZ  33554432
#define OFF_FEAT  35397632
#define OFF_QST   153362432
#define OFF_LOSS  271327232

// Scratch
__device__ float g_partial[BB];

// Pre-transposed weights (stride-68 rows, 16B-aligned)
#define GW_W1T   0
#define GW_W2T   6528
#define GW_W3T   19584
#define GW_DW1T  32640
#define GW_DW2T  45696
#define GW_DW3T  63104
#define GW_OWT   71808
__device__ __align__(16) float g_wt[76032];

__global__ void prep_kernel(const float* __restrict__ w1, const float* __restrict__ w2,
                            const float* __restrict__ w3, const float* __restrict__ dw1,
                            const float* __restrict__ dw2, const float* __restrict__ dw3,
                            const float* __restrict__ ow)
{
    const int tid = blockIdx.x * blockDim.x + threadIdx.x;
    const int nt  = gridDim.x * blockDim.x;
    for (int i = tid; i < 6144; i += nt) {
        int o = i / 96, r = i - o * 96;
        g_wt[GW_W1T + r * 68 + o] = w1[i];
    }
    for (int i = tid; i < 12288; i += nt) {
        int o = i / 192, r = i - o * 192;
        g_wt[GW_W2T + r * 68 + o] = w2[i];
    }
    for (int i = tid; i < 12288; i += nt) {
        int o = i / 192, r = i - o * 192;
        g_wt[GW_W3T + r * 68 + o] = w3[i];
    }
    for (int i = tid; i < 12288; i += nt) {
        int q = i >> 6, o = i & 63;
        g_wt[GW_DW1T + q * 68 + o] = dw1[(q / 3) * 192 + o * 3 + (q % 3)];
    }
    for (int i = tid; i < 16384; i += nt) {
        int q = i >> 6, o = i & 63;
        g_wt[GW_DW2T + q * 68 + o] = dw2[(q >> 2) * 256 + o * 4 + (q & 3)];
    }
    for (int i = tid; i < 8192; i += nt) {
        int q = i >> 5, o = i & 31;
        g_wt[GW_DW3T + q * 34 + o] = dw3[(q >> 2) * 128 + o * 4 + (q & 3)];
    }
    for (int i = tid; i < 4096; i += nt) {
        int v = i >> 5, e = i & 31;
        g_wt[GW_OWT + e * 132 + v] = ow[i];
    }
}

// ---------------- Fused shared layout (floats) ----------------
// A (4608) @0    : enc: X[32][132](4224) -> H2[64][34]@0 + ENC[30][64]@2176
//                  dec: F[64][36]@0 + G1[64][36]@2304 -> G3[32][132]@0
// B (4352) @4608 : enc: H1[64][68]  dec: G2[64][68]
// CB (640) @8960 ; DIST (304) @9600
#define SM_A     0
#define SM_B     4608
#define SM_CB    8960
#define SM_DIST  9600
#define SM_FLOATS 9904
#define SM_BYTES  (SM_FLOATS * 4)

#define A_H2   0
#define A_ENC  2176
#define A_F    0
#define A_G1   2304
#define A_G3   0

__global__ void __launch_bounds__(256, 4)
fused_kernel(const int* __restrict__ ti, const float* __restrict__ emb,
             const float* __restrict__ b1, const float* __restrict__ b2,
             const float* __restrict__ b3, const float* __restrict__ cb,
             const float* __restrict__ db1, const float* __restrict__ db2,
             const float* __restrict__ db3, const float* __restrict__ ob,
             float* __restrict__ out_logits,
             float* __restrict__ out_feat, float* __restrict__ out_qst,
             float* __restrict__ out_puzz)
{
    extern __shared__ float s[];
    float* X   = s + SM_A;
    float* H1  = s + SM_B;
    float* CB  = s + SM_CB;
    float* DIST= s + SM_DIST;
    float* H2  = s + SM_A + A_H2;
    float* ENC = s + SM_A + A_ENC;
    float* F   = s + SM_A + A_F;
    float* G1  = s + SM_A + A_G1;
    float* G2  = s + SM_B;
    float* G3  = s + SM_A + A_G3;
    __shared__ int   codes_s[30];
    __shared__ float mind_s[30];

    const int tid = threadIdx.x;
    const int b   = blockIdx.x;

    // ================= ENCODER =================
    for (int i = tid; i < 4224; i += 256) X[i] = 0.f;
    for (int i = tid; i < 4352; i += 256) H1[i] = 0.f;
    for (int i = tid; i < 640; i += 256) CB[i] = cb[i];
    __syncthreads();

    // gather: X[e][l+1] = emb[ti[l]*32 + e]
    const int* tirow = ti + b * LL;
    for (int i = tid; i < LL * 32; i += 256) {
        int l = i >> 5, e = i & 31;
        X[e * 132 + l + 1] = emb[tirow[l] * 32 + e];
    }
    __syncthreads();

    // conv1: X [32][128] pad1 s2 k3 -> H1 [64][64], ReLU.  4o x 4t, f32x2, direct-LDG weights
    {
        const int o0 = (tid & 15) * 4;
        const int t0 = (tid >> 4) * 4;
        u64 a01[4], a23[4];
        {
            u64 bb01 = pk2(__ldg(&b1[o0]), __ldg(&b1[o0 + 1]));
            u64 bb23 = pk2(__ldg(&b1[o0 + 2]), __ldg(&b1[o0 + 3]));
            #pragma unroll
            for (int t = 0; t < 4; t++) { a01[t] = bb01; a23[t] = bb23; }
        }
        #pragma unroll 2
        for (int e = 0; e < 32; e++) {
            const float* xr = &X[e * 132 + 2 * t0];
            float4 v0 = *(const float4*)xr;
            float4 v1 = *(const float4*)(xr + 4);
            float x8 = xr[8];
            u64 xp[9];
            xp[0]=pk(v0.x); xp[1]=pk(v0.y); xp[2]=pk(v0.z); xp[3]=pk(v0.w);
            xp[4]=pk(v1.x); xp[5]=pk(v1.y); xp[6]=pk(v1.z); xp[7]=pk(v1.w);
            xp[8]=pk(x8);
            const float* wrow = g_wt + GW_W1T + (e * 3) * 68 + o0;
            #pragma unroll
            for (int k = 0; k < 3; k++) {
                const u64* wp = (const u64*)(wrow + k * 68);
                u64 w01 = __ldg(wp), w23 = __ldg(wp + 1);
                #pragma unroll
                for (int t = 0; t < 4; t++) {
                    fma2(a01[t], w01, xp[2 * t + k]);
                    fma2(a23[t], w23, xp[2 * t + k]);
                }
            }
        }
        __syncthreads();
        #pragma unroll
        for (int t = 0; t < 4; t++) {
            float2 p01 = upk(a01[t]), p23 = upk(a23[t]);
            H1[(o0 + 0) * 68 + t0 + t + 1] = fmaxf(p01.x, 0.f);
            H1[(o0 + 1) * 68 + t0 + t + 1] = fmaxf(p01.y, 0.f);
            H1[(o0 + 2) * 68 + t0 + t + 1] = fmaxf(p23.x, 0.f);
            H1[(o0 + 3) * 68 + t0 + t + 1] = fmaxf(p23.y, 0.f);
        }
    }
    __syncthreads();

    // conv2: H1 [64][64] pad1 s2 k3 -> H2 [64][32] (stride 34), ReLU.  4o x 2t, f32x2
    {
        const int o0 = (tid & 15) * 4;
        const int t0 = (tid >> 4) * 2;
        u64 a01[2], a23[2];
        {
            u64 bb01 = pk2(__ldg(&b2[o0]), __ldg(&b2[o0 + 1]));
            u64 bb23 = pk2(__ldg(&b2[o0 + 2]), __ldg(&b2[o0 + 3]));
            a01[0] = a01[1] = bb01;
            a23[0] = a23[1] = bb23;
        }
        #pragma unroll 2
        for (int e = 0; e < 64; e++) {
            const float* xr = &H1[e * 68 + 2 * t0];
            float4 v = *(const float4*)xr;
            float x4 = xr[4];
            u64 xp[5];
            xp[0]=pk(v.x); xp[1]=pk(v.y); xp[2]=pk(v.z); xp[3]=pk(v.w); xp[4]=pk(x4);
            const float* wrow = g_wt + GW_W2T + (e * 3) * 68 + o0;
            #pragma unroll
            for (int k = 0; k < 3; k++) {
                const u64* wp = (const u64*)(wrow + k * 68);
                u64 w01 = __ldg(wp), w23 = __ldg(wp + 1);
                #pragma unroll
                for (int t = 0; t < 2; t++) {
                    fma2(a01[t], w01, xp[2 * t + k]);
                    fma2(a23[t], w23, xp[2 * t + k]);
                }
            }
        }
        __syncthreads();
        #pragma unroll
        for (int t = 0; t < 2; t++) {
            float2 p01 = upk(a01[t]), p23 = upk(a23[t]);
            H2[(o0 + 0) * 34 + t0 + t] = fmaxf(p01.x, 0.f);
            H2[(o0 + 1) * 34 + t0 + t] = fmaxf(p01.y, 0.f);
            H2[(o0 + 2) * 34 + t0 + t] = fmaxf(p23.x, 0.f);
            H2[(o0 + 3) * 34 + t0 + t] = fmaxf(p23.y, 0.f);
        }
    }
    __syncthreads();

    // conv3: H2 [64][32] pad0 s1 k3 -> ENC [30][64] transposed.  2o x 5t, 192 act, f32x2
    {
        const bool act = tid < 192;
        const int o0 = (tid & 31) * 2;
        const int t0 = (tid >> 5) * 5;
        u64 ap[5];
        if (act) {
            u64 bb = pk2(__ldg(&b3[o0]), __ldg(&b3[o0 + 1]));
            #pragma unroll
            for (int t = 0; t < 5; t++) ap[t] = bb;
            #pragma unroll 2
            for (int e = 0; e < 64; e++) {
                const float* xr = &H2[e * 34 + t0];
                u64 xp[7];
                #pragma unroll
                for (int u = 0; u < 7; u++) xp[u] = pk(xr[u]);
                const float* wrow = g_wt + GW_W3T + (e * 3) * 68 + o0;
                #pragma unroll
                for (int k = 0; k < 3; k++) {
                    u64 w = __ldg((const u64*)(wrow + k * 68));
                    #pragma unroll
                    for (int t = 0; t < 5; t++) fma2(ap[t], w, xp[t + k]);
                }
            }
        }
        __syncthreads();
        if (act) {
            #pragma unroll
            for (int t = 0; t < 5; t++) {
                float2 p = upk(ap[t]);
                ENC[(t0 + t) * 64 + o0]     = p.x;
                ENC[(t0 + t) * 64 + o0 + 1] = p.y;
            }
        }
    }
    __syncthreads();

    // VQ distances + argmin
    for (int idx = tid; idx < 300; idx += 256) {
        int i = idx / 10, c = idx - i * 10;
        const float* fe = &ENC[i * 64];
        const float* cc = &CB[c * 64];
        float acc = 0.f;
        #pragma unroll 8
        for (int d = 0; d < 64; d++) { float df = fe[d] - cc[d]; acc += df * df; }
        DIST[i * 10 + c] = acc;
    }
    __syncthreads();
    if (tid < 30) {
        float mv = DIST[tid * 10]; int mc = 0;
        #pragma unroll
        for (int c = 1; c < 10; c++) {
            float v = DIST[tid * 10 + c];
            if (v < mv) { mv = v; mc = c; }
        }
        codes_s[tid] = mc;
        mind_s[tid] = mv;
    }
    __syncthreads();
    if (tid == 0) {
        float acc = 0.f;
        #pragma unroll
        for (int i = 0; i < 30; i++) acc += mind_s[i];
        g_partial[b] = acc;
    }

    // ---- broadcast stores (register-cached, streaming); drain overlaps decoder ----
    {
        float* puz = out_puzz + (size_t)b * 900;
        for (int idx = tid; idx < 900; idx += 256)
            __stcs(&puz[idx], (float)codes_s[idx / 30]);

        const float4* enc4 = (const float4*)ENC;
        const float4* cb4  = (const float4*)CB;
        float4* f4 = (float4*)out_feat + (size_t)b * 14400;
        float4* q4 = (float4*)out_qst  + (size_t)b * 14400;
        const int lane = tid & 31;
        const int wid  = tid >> 5;
        const int q    = lane & 15;
        const int jh   = lane >> 4;
        for (int i = wid; i < 30; i += 8) {
            float4 ev = enc4[i * 16 + q];
            float4 cv = cb4[codes_s[i] * 16 + q];
            float4* fb = f4 + i * 480 + jh * 16 + q;
            float4* qb = q4 + i * 480 + jh * 16 + q;
            #pragma unroll
            for (int j = 0; j < 30; j += 2) {
                __stcs(fb + j * 16, ev);
                __stcs(qb + j * 16, cv);
            }
        }
    }
    __syncthreads();

    // ================= DECODER =================
    for (int i = tid; i < 4608; i += 256) s[SM_A + i] = 0.f;
    for (int i = tid; i < 4352; i += 256) G2[i] = 0.f;
    __syncthreads();

    // F[d][i+2] = codebook[code[i]][d]
    for (int idx = tid; idx < 64 * 30; idx += 256) {
        int d = idx / 30, i = idx - d * 30;
        F[d * 36 + i + 2] = CB[codes_s[i] * 64 + d];
    }
    __syncthreads();

    // convT1: F [64][30] s1 p0 k3 -> G1 [64][32], ReLU.  2o x 4t, f32x2
    {
        const int o0 = (tid & 31) * 2;
        const int t0 = (tid >> 5) * 4;
        u64 ap[4];
        {
            u64 bb = pk2(__ldg(&db1[o0]), __ldg(&db1[o0 + 1]));
            #pragma unroll
            for (int t = 0; t < 4; t++) ap[t] = bb;
        }
        #pragma unroll 2
        for (int cl = 0; cl < 64; cl++) {
            const float* xr = &F[cl * 36 + t0];
            float4 v = *(const float4*)xr;
            float2 v2 = *(const float2*)(xr + 4);
            u64 xp[6];
            xp[0]=pk(v.x); xp[1]=pk(v.y); xp[2]=pk(v.z); xp[3]=pk(v.w);
            xp[4]=pk(v2.x); xp[5]=pk(v2.y);
            const float* wrow = g_wt + GW_DW1T + (cl * 3) * 68 + o0;
            #pragma unroll
            for (int k = 0; k < 3; k++) {
                u64 w = __ldg((const u64*)(wrow + k * 68));
                #pragma unroll
                for (int t = 0; t < 4; t++) fma2(ap[t], w, xp[t + 2 - k]);
            }
        }
        __syncthreads();
        #pragma unroll
        for (int t = 0; t < 4; t++) {
            float2 p = upk(ap[t]);
            G1[o0 * 36 + t0 + t + 1]       = fmaxf(p.x, 0.f);
            G1[(o0 + 1) * 36 + t0 + t + 1] = fmaxf(p.y, 0.f);
        }
    }
    __syncthreads();

    // convT2: G1 [64][32] s2 p1 k4 -> G2 [64][64], ReLU.  2o x 8t, f32x2
    {
        const int oo = (tid & 31) * 2;
        const int tt0 = (tid >> 5) * 8;
        u64 ap[8];
        {
            u64 bb = pk2(__ldg(&db2[oo]), __ldg(&db2[oo + 1]));
            #pragma unroll
            for (int t = 0; t < 8; t++) ap[t] = bb;
        }
        #pragma unroll 2
        for (int cl = 0; cl < 64; cl++) {
            const float* xr = &G1[cl * 36 + (tt0 >> 1)];
            float4 v = *(const float4*)xr;
            float2 v2 = *(const float2*)(xr + 4);
            u64 xp[6];
            xp[0]=pk(v.x); xp[1]=pk(v.y); xp[2]=pk(v.z); xp[3]=pk(v.w);
            xp[4]=pk(v2.x); xp[5]=pk(v2.y);
            const float* wb = g_wt + GW_DW2T + (cl * 4) * 68 + oo;
            u64 w0 = __ldg((const u64*)(wb));
            u64 w1 = __ldg((const u64*)(wb + 68));
            u64 w2 = __ldg((const u64*)(wb + 136));
            u64 w3 = __ldg((const u64*)(wb + 204));
            #pragma unroll
            for (int t = 0; t < 8; t++) {
                int u1 = ((t + 1) >> 1) + 1;
                if (t & 1) {
                    fma2(ap[t], w0, xp[u1]);
                    fma2(ap[t], w2, xp[u1 - 1]);
                } else {
                    fma2(ap[t], w1, xp[u1]);
                    fma2(ap[t], w3, xp[u1 - 1]);
                }
            }
        }
        __syncthreads();
        #pragma unroll
        for (int t = 0; t < 8; t++) {
            float2 p = upk(ap[t]);
            G2[oo * 68 + tt0 + t + 1]       = fmaxf(p.x, 0.f);
            G2[(oo + 1) * 68 + tt0 + t + 1] = fmaxf(p.y, 0.f);
        }
    }
    __syncthreads();

    // convT3: G2 [64][64] s2 p1 k4 -> G3 [32][128] (aliases F/G1).  2o x 8t, f32x2
    {
        const int oo = (tid & 15) * 2;
        const int tt0 = (tid >> 4) * 8;
        u64 ap[8];
        {
            u64 bb = pk2(__ldg(&db3[oo]), __ldg(&db3[oo + 1]));
            #pragma unroll
            for (int t = 0; t < 8; t++) ap[t] = bb;
        }
        #pragma unroll 2
        for (int cl = 0; cl < 64; cl++) {
            const float* xr = &G2[cl * 68 + (tt0 >> 1)];
            float4 v = *(const float4*)xr;
            float2 v2 = *(const float2*)(xr + 4);
            u64 xp[6];
            xp[0]=pk(v.x); xp[1]=pk(v.y); xp[2]=pk(v.z); xp[3]=pk(v.w);
            xp[4]=pk(v2.x); xp[5]=pk(v2.y);
            const float* wb = g_wt + GW_DW3T + (cl * 4) * 34 + oo;
            u64 w0 = __ldg((const u64*)(wb));
            u64 w1 = __ldg((const u64*)(wb + 34));
            u64 w2 = __ldg((const u64*)(wb + 68));
            u64 w3 = __ldg((const u64*)(wb + 102));
            #pragma unroll
            for (int t = 0; t < 8; t++) {
                int u1 = ((t + 1) >> 1) + 1;
                if (t & 1) {
                    fma2(ap[t], w0, xp[u1]);
                    fma2(ap[t], w2, xp[u1 - 1]);
                } else {
                    fma2(ap[t], w1, xp[u1]);
                    fma2(ap[t], w3, xp[u1 - 1]);
                }
            }
        }
        __syncthreads();   // all G1 reads done before aliased G3 writes
        #pragma unroll
        for (int t = 0; t < 8; t++) {
            float2 p = upk(ap[t]);
            G3[oo * 132 + tt0 + t]       = p.x;
            G3[(oo + 1) * 132 + tt0 + t] = p.y;
        }
    }
    __syncthreads();

    // final GEMM: logits[l][v] = sum_e G3[e][l] * ow[v*32+e] + ob[v].  4v x 8l x2, f32x2
    {
        const int v0 = (tid & 31) * 4;
        const int l0 = (tid >> 5) * 16;
        u64 b01 = pk2(__ldg(&ob[v0]), __ldg(&ob[v0 + 1]));
        u64 b23 = pk2(__ldg(&ob[v0 + 2]), __ldg(&ob[v0 + 3]));
        #pragma unroll
        for (int lh = 0; lh < 2; lh++) {
            const int l = l0 + lh * 8;
            u64 g01[8], g23[8];
            #pragma unroll
            for (int u = 0; u < 8; u++) { g01[u] = b01; g23[u] = b23; }
            #pragma unroll 2
            for (int e = 0; e < 32; e++) {
                const float* xr = &G3[e * 132 + l];
                float4 va = *(const float4*)xr;
                float4 vb = *(const float4*)(xr + 4);
                u64 xp[8];
                xp[0]=pk(va.x); xp[1]=pk(va.y); xp[2]=pk(va.z); xp[3]=pk(va.w);
                xp[4]=pk(vb.x); xp[5]=pk(vb.y); xp[6]=pk(vb.z); xp[7]=pk(vb.w);
                const u64* wp = (const u64*)(g_wt + GW_OWT + e * 132 + v0);
                u64 w01 = __ldg(wp), w23 = __ldg(wp + 1);
                #pragma unroll
                for (int u = 0; u < 8; u++) {
                    fma2(g01[u], w01, xp[u]);
                    fma2(g23[u], w23, xp[u]);
                }
            }
            float* outp = out_logits + ((size_t)b * 128 + l) * 128 + v0;
            #pragma unroll
            for (int u = 0; u < 8; u++) {
                float2 p01 = upk(g01[u]), p23 = upk(g23[u]);
                float4 vv = make_float4(p01.x, p01.y, p23.x, p23.y);
                __stcs((float4*)(outp + (size_t)u * 128), vv);
            }
        }
    }
}

// Deterministic loss reduce
__global__ void loss_kernel(float* __restrict__ out_loss)
{
    __shared__ float sm[256];
    float a = 0.f;
    for (int i = threadIdx.x; i < BB; i += 256) a += g_partial[i];
    sm[threadIdx.x] = a;
    __syncthreads();
    for (int sft = 128; sft > 0; sft >>= 1) {
        if (threadIdx.x < sft) sm[threadIdx.x] += sm[threadIdx.x + sft];
        __syncthreads();
    }
    if (threadIdx.x == 0)
        out_loss[0] = sm[0] * (1.25f / (2048.f * 30.f * 64.f));
}

extern "C" void kernel_launch(void* const* d_in, const int* in_sizes, int n_in,
                              void* d_out, int out_size)
{
    const int*   ti     = (const int*)  d_in[0];
    const float* emb    = (const float*)d_in[1];
    const float* enc_w1 = (const float*)d_in[2];
    const float* enc_b1 = (const float*)d_in[3];
    const float* enc_w2 = (const float*)d_in[4];
    const float* enc_b2 = (const float*)d_in[5];
    const float* enc_w3 = (const float*)d_in[6];
    const float* enc_b3 = (const float*)d_in[7];
    const float* cb     = (const float*)d_in[8];
    const float* dec_w1 = (const float*)d_in[9];
    const float* dec_b1 = (const float*)d_in[10];
    const float* dec_w2 = (const float*)d_in[11];
    const float* dec_b2 = (const float*)d_in[12];
    const float* dec_w3 = (const float*)d_in[13];
    const float* dec_b3 = (const float*)d_in[14];
    const float* out_w  = (const float*)d_in[15];
    const float* out_b  = (const float*)d_in[16];

    float* out        = (float*)d_out;
    float* out_logits = out;
    float* out_puzz   = out + OFF_PUZZ;
    float* out_feat   = out + OFF_FEAT;
    float* out_qst    = out + OFF_QST;
    float* out_loss   = out + OFF_LOSS;

    cudaFuncSetAttribute(fused_kernel, cudaFuncAttributeMaxDynamicSharedMemorySize, SM_BYTES);

    prep_kernel<<<64, 256>>>(enc_w1, enc_w2, enc_w3, dec_w1, dec_w2, dec_w3, out_w);
    fused_kernel<<<BB, 256, SM_BYTES>>>(ti, emb, enc_b1, enc_b2, enc_b3, cb,
                                        dec_b1, dec_b2, dec_b3, out_b,
                                        out_logits, out_feat, out_qst, out_puzz);
    loss_kernel<<<1, 256>>>(out_loss);
}

// round 11
// speedup vs baseline: 1.2423x; 1.2423x over previous
#include <cuda_runtime.h>
#include <cstdint>

typedef unsigned long long u64;

__device__ __forceinline__ u64 pk(float x) {
    u64 r; asm("mov.b64 %0, {%1, %1};" : "=l"(r) : "f"(x)); return r;
}
__device__ __forceinline__ u64 pk2(float x, float y) {
    u64 r; asm("mov.b64 %0, {%1, %2};" : "=l"(r) : "f"(x), "f"(y)); return r;
}
__device__ __forceinline__ void fma2(u64& d, u64 a, u64 b) {
    asm("fma.rn.f32x2 %0, %1, %2, %0;" : "+l"(d) : "l"(a), "l"(b));
}
__device__ __forceinline__ void add2(u64& d, u64 a) {
    asm("add.rn.f32x2 %0, %1, %0;" : "+l"(d) : "l"(a));
}
__device__ __forceinline__ float2 upk(u64 v) {
    float2 r; asm("mov.b64 {%0, %1}, %2;" : "=f"(r.x), "=f"(r.y) : "l"(v)); return r;
}

// Problem constants
#define BB   2048
#define LL   128

// Output layout (concatenated, float32)
#define OFF_PUZZ  33554432
#define OFF_FEAT  35397632
#define OFF_QST   153362432
#define OFF_LOSS  271327232

// Scratch
__device__ float g_partial[BB];

// Pre-transposed weights + tables (stride-68/34 rows, 16B-aligned)
#define GW_W2T   0
#define GW_W3T   13056
#define GW_DW2T  26112
#define GW_DW3T  43520
#define GW_OWT   52224
#define GW_T1    56448
#define GW_M1    82764
__device__ __align__(16) float g_wt[85008];

__global__ void prep_kernel(const float* __restrict__ w1, const float* __restrict__ w2,
                            const float* __restrict__ w3, const float* __restrict__ dw1,
                            const float* __restrict__ dw2, const float* __restrict__ dw3,
                            const float* __restrict__ ow, const float* __restrict__ emb,
                            const float* __restrict__ cb)
{
    const int tid = blockIdx.x * blockDim.x + threadIdx.x;
    const int nt  = gridDim.x * blockDim.x;
    for (int i = tid; i < 12288; i += nt) {
        int o = i / 192, r = i - o * 192;
        g_wt[GW_W2T + r * 68 + o] = w2[i];
    }
    for (int i = tid; i < 12288; i += nt) {
        int o = i / 192, r = i - o * 192;
        g_wt[GW_W3T + r * 68 + o] = w3[i];
    }
    for (int i = tid; i < 16384; i += nt) {
        int q = i >> 6, o = i & 63;
        g_wt[GW_DW2T + q * 68 + o] = dw2[(q >> 2) * 256 + o * 4 + (q & 3)];
    }
    for (int i = tid; i < 8192; i += nt) {
        int q = i >> 5, o = i & 31;
        g_wt[GW_DW3T + q * 34 + o] = dw3[(q >> 2) * 128 + o * 4 + (q & 3)];
    }
    for (int i = tid; i < 4096; i += nt) {
        int v = i >> 5, e = i & 31;
        g_wt[GW_OWT + e * 132 + v] = ow[i];
    }
    // T1[k][v][o] = sum_e w1[o][e][k] * emb[v][e]; slot v=128 is zeros (padding)
    for (int idx = tid; idx < 3 * 129 * 64; idx += nt) {
        int o = idx & 63;
        int q = idx >> 6;          // k*129 + v
        int k = q / 129, v = q - k * 129;
        float acc = 0.f;
        if (v < 128) {
            for (int e = 0; e < 32; e++)
                acc += w1[o * 96 + e * 3 + k] * emb[v * 32 + e];
        }
        g_wt[GW_T1 + q * 68 + o] = acc;
    }
    // M1[k][cd][o] = sum_c dw1[c][o][k] * cb[cd][c]; slot cd=10 is zeros
    for (int idx = tid; idx < 3 * 11 * 64; idx += nt) {
        int o = idx & 63;
        int q = idx >> 6;          // k*11 + cd
        int k = q / 11, cd = q - k * 11;
        float acc = 0.f;
        if (cd < 10) {
            for (int c = 0; c < 64; c++)
                acc += dw1[c * 192 + o * 3 + k] * cb[cd * 64 + c];
        }
        g_wt[GW_M1 + q * 68 + o] = acc;
    }
}

// ---------------- Fused shared layout (floats) ----------------
// A (4608) @0    : enc: H2[64][34]@0 + ENC[30][64]@2176
//                  dec: G1[64][36]@0 -> G3[32][132]@0
// B (4352) @4608 : enc: H1[64][68]  dec: G2[64][68]
// WT (4352) @8960 ; CB (640) @13312 ; DIST (304) @13952
#define SM_A     0
#define SM_B     4608
#define SM_WT    8960
#define SM_CB    13312
#define SM_DIST  13952
#define SM_FLOATS 14256
#define SM_BYTES  (SM_FLOATS * 4)

#define A_H2   0
#define A_ENC  2176
#define A_G1   0
#define A_G3   0

__global__ void __launch_bounds__(256, 4)
fused_kernel(const int* __restrict__ ti,
             const float* __restrict__ b1, const float* __restrict__ b2,
             const float* __restrict__ b3, const float* __restrict__ cb,
             const float* __restrict__ db1, const float* __restrict__ db2,
             const float* __restrict__ db3, const float* __restrict__ ob,
             float* __restrict__ out_logits,
             float* __restrict__ out_feat, float* __restrict__ out_qst,
             float* __restrict__ out_puzz)
{
    extern __shared__ float s[];
    float* H1  = s + SM_B;
    float* WT  = s + SM_WT;
    float* CB  = s + SM_CB;
    float* DIST= s + SM_DIST;
    float* H2  = s + SM_A + A_H2;
    float* ENC = s + SM_A + A_ENC;
    float* G1  = s + SM_A + A_G1;
    float* G2  = s + SM_B;
    float* G3  = s + SM_A + A_G3;
    __shared__ int   codes_s[30];
    __shared__ float mind_s[30];
    __shared__ int   tok_s[129];

    const int tid = threadIdx.x;
    const int b   = blockIdx.x;

    // ================= ENCODER =================
    for (int i = tid; i < 4352; i += 256) H1[i] = 0.f;
    for (int i = tid; i < 640; i += 256) CB[i] = cb[i];
    // tokens with left sentinel (slot 128 = zero row of T1)
    if (tid < 129) tok_s[tid] = (tid == 0) ? 128 : __ldg(&ti[b * LL + tid - 1]);
    __syncthreads();

    // conv1 via T1 table: H1[o][t+1] = relu(b1[o] + sum_k T1[k][tok_s[2t+k]][o]).  4o x 4t
    {
        const int o0 = (tid & 15) * 4;
        const int t0 = (tid >> 4) * 4;
        u64 a01[4], a23[4];
        {
            u64 bb01 = pk2(__ldg(&b1[o0]), __ldg(&b1[o0 + 1]));
            u64 bb23 = pk2(__ldg(&b1[o0 + 2]), __ldg(&b1[o0 + 3]));
            #pragma unroll
            for (int t = 0; t < 4; t++) { a01[t] = bb01; a23[t] = bb23; }
        }
        int tk[9];
        #pragma unroll
        for (int u = 0; u < 9; u++) tk[u] = tok_s[2 * t0 + u];
        #pragma unroll
        for (int k = 0; k < 3; k++) {
            #pragma unroll
            for (int t = 0; t < 4; t++) {
                const u64* p = (const u64*)(g_wt + GW_T1 + (k * 129 + tk[2 * t + k]) * 68 + o0);
                add2(a01[t], __ldg(p));
                add2(a23[t], __ldg(p + 1));
            }
        }
        #pragma unroll
        for (int t = 0; t < 4; t++) {
            float2 p01 = upk(a01[t]), p23 = upk(a23[t]);
            H1[(o0 + 0) * 68 + t0 + t + 1] = fmaxf(p01.x, 0.f);
            H1[(o0 + 1) * 68 + t0 + t + 1] = fmaxf(p01.y, 0.f);
            H1[(o0 + 2) * 68 + t0 + t + 1] = fmaxf(p23.x, 0.f);
            H1[(o0 + 3) * 68 + t0 + t + 1] = fmaxf(p23.y, 0.f);
        }
    }
    __syncthreads();

    // conv2: H1 [64][64] pad1 s2 k3 -> H2 [64][32] (stride 34), ReLU.  4o x 2t, f32x2, staged chunks
    {
        const int o0 = (tid & 15) * 4;
        const int t0 = (tid >> 4) * 2;
        u64 a01[2], a23[2];
        #pragma unroll
        for (int ch = 0; ch < 4; ch++) {
            __syncthreads();
            const float4* src = (const float4*)(g_wt + GW_W2T + ch * 3264);
            for (int i = tid; i < 816; i += 256) ((float4*)WT)[i] = src[i];
            __syncthreads();
            if (ch == 0) {
                u64 bb01 = pk2(__ldg(&b2[o0]), __ldg(&b2[o0 + 1]));
                u64 bb23 = pk2(__ldg(&b2[o0 + 2]), __ldg(&b2[o0 + 3]));
                a01[0] = a01[1] = bb01;
                a23[0] = a23[1] = bb23;
            }
            for (int el = 0; el < 16; el++) {
                const float* xr = &H1[(ch * 16 + el) * 68 + 2 * t0];
                float4 v = *(const float4*)xr;
                float x4 = xr[4];
                u64 xp[5];
                xp[0]=pk(v.x); xp[1]=pk(v.y); xp[2]=pk(v.z); xp[3]=pk(v.w); xp[4]=pk(x4);
                #pragma unroll
                for (int k = 0; k < 3; k++) {
                    const u64* wp = (const u64*)&WT[(el * 3 + k) * 68 + o0];
                    u64 w01 = wp[0], w23 = wp[1];
                    #pragma unroll
                    for (int t = 0; t < 2; t++) {
                        fma2(a01[t], w01, xp[2 * t + k]);
                        fma2(a23[t], w23, xp[2 * t + k]);
                    }
                }
            }
        }
        __syncthreads();
        #pragma unroll
        for (int t = 0; t < 2; t++) {
            float2 p01 = upk(a01[t]), p23 = upk(a23[t]);
            H2[(o0 + 0) * 34 + t0 + t] = fmaxf(p01.x, 0.f);
            H2[(o0 + 1) * 34 + t0 + t] = fmaxf(p01.y, 0.f);
            H2[(o0 + 2) * 34 + t0 + t] = fmaxf(p23.x, 0.f);
            H2[(o0 + 3) * 34 + t0 + t] = fmaxf(p23.y, 0.f);
        }
    }
    __syncthreads();

    // conv3: H2 [64][32] pad0 s1 k3 -> ENC [30][64] transposed.  2o x 5t, 192 act, staged chunks
    {
        const bool act = tid < 192;
        const int o0 = (tid & 31) * 2;
        const int t0 = (tid >> 5) * 5;
        u64 ap[5];
        #pragma unroll
        for (int ch = 0; ch < 4; ch++) {
            __syncthreads();
            const float4* src = (const float4*)(g_wt + GW_W3T + ch * 3264);
            for (int i = tid; i < 816; i += 256) ((float4*)WT)[i] = src[i];
            __syncthreads();
            if (act) {
                if (ch == 0) {
                    u64 bb = pk2(__ldg(&b3[o0]), __ldg(&b3[o0 + 1]));
                    #pragma unroll
                    for (int t = 0; t < 5; t++) ap[t] = bb;
                }
                for (int el = 0; el < 16; el++) {
                    const float* xr = &H2[(ch * 16 + el) * 34 + t0];
                    u64 xp[7];
                    #pragma unroll
                    for (int u = 0; u < 7; u++) xp[u] = pk(xr[u]);
                    #pragma unroll
                    for (int k = 0; k < 3; k++) {
                        u64 w = *(const u64*)&WT[(el * 3 + k) * 68 + o0];
                        #pragma unroll
                        for (int t = 0; t < 5; t++) fma2(ap[t], w, xp[t + k]);
                    }
                }
            }
        }
        __syncthreads();
        if (act) {
            #pragma unroll
            for (int t = 0; t < 5; t++) {
                float2 p = upk(ap[t]);
                ENC[(t0 + t) * 64 + o0]     = p.x;
                ENC[(t0 + t) * 64 + o0 + 1] = p.y;
            }
        }
    }
    __syncthreads();

    // VQ distances + argmin
    for (int idx = tid; idx < 300; idx += 256) {
        int i = idx / 10, c = idx - i * 10;
        const float* fe = &ENC[i * 64];
        const float* cc = &CB[c * 64];
        float acc = 0.f;
        #pragma unroll 8
        for (int d = 0; d < 64; d++) { float df = fe[d] - cc[d]; acc += df * df; }
        DIST[i * 10 + c] = acc;
    }
    __syncthreads();
    if (tid < 30) {
        float mv = DIST[tid * 10]; int mc = 0;
        #pragma unroll
        for (int c = 1; c < 10; c++) {
            float v = DIST[tid * 10 + c];
            if (v < mv) { mv = v; mc = c; }
        }
        codes_s[tid] = mc;
        mind_s[tid] = mv;
    }
    __syncthreads();
    if (tid == 0) {
        float acc = 0.f;
        #pragma unroll
        for (int i = 0; i < 30; i++) acc += mind_s[i];
        g_partial[b] = acc;
    }

    // ---- broadcast stores (register-cached, streaming); drain overlaps decoder ----
    {
        float* puz = out_puzz + (size_t)b * 900;
        for (int idx = tid; idx < 900; idx += 256)
            __stcs(&puz[idx], (float)codes_s[idx / 30]);

        const float4* enc4 = (const float4*)ENC;
        const float4* cb4  = (const float4*)CB;
        float4* f4 = (float4*)out_feat + (size_t)b * 14400;
        float4* q4 = (float4*)out_qst  + (size_t)b * 14400;
        const int lane = tid & 31;
        const int wid  = tid >> 5;
        const int q    = lane & 15;
        const int jh   = lane >> 4;
        for (int i = wid; i < 30; i += 8) {
            float4 ev = enc4[i * 16 + q];
            float4 cv = cb4[codes_s[i] * 16 + q];
            float4* fb = f4 + i * 480 + jh * 16 + q;
            float4* qb = q4 + i * 480 + jh * 16 + q;
            #pragma unroll
            for (int j = 0; j < 30; j += 2) {
                __stcs(fb + j * 16, ev);
                __stcs(qb + j * 16, cv);
            }
        }
    }
    __syncthreads();

    // ================= DECODER =================
    // zero G1 region + G2 halos; stage M1 into WT
    for (int i = tid; i < 2304; i += 256) s[SM_A + i] = 0.f;
    for (int i = tid; i < 4352; i += 256) G2[i] = 0.f;
    {
        const float4* src = (const float4*)(g_wt + GW_M1);
        for (int i = tid; i < 561; i += 256) ((float4*)WT)[i] = src[i];
    }
    __syncthreads();

    // convT1 via M1 table: G1[o][p+1] = relu(db1[o] + sum_k M1[k][code(p-k)][o]).  4o x 4p, 128 act
    if (tid < 128) {
        const int o0 = (tid & 15) * 4;
        const int p0 = (tid >> 4) * 4;
        u64 a01[4], a23[4];
        {
            u64 bb01 = pk2(__ldg(&db1[o0]), __ldg(&db1[o0 + 1]));
            u64 bb23 = pk2(__ldg(&db1[o0 + 2]), __ldg(&db1[o0 + 3]));
            #pragma unroll
            for (int t = 0; t < 4; t++) { a01[t] = bb01; a23[t] = bb23; }
        }
        #pragma unroll
        for (int k = 0; k < 3; k++) {
            #pragma unroll
            for (int t = 0; t < 4; t++) {
                int i = p0 + t - k;
                int cd = ((unsigned)i < 30u) ? codes_s[i] : 10;
                const u64* mp = (const u64*)&WT[(k * 11 + cd) * 68 + o0];
                add2(a01[t], mp[0]);
                add2(a23[t], mp[1]);
            }
        }
        #pragma unroll
        for (int t = 0; t < 4; t++) {
            float2 p01 = upk(a01[t]), p23 = upk(a23[t]);
            G1[(o0 + 0) * 36 + p0 + t + 1] = fmaxf(p01.x, 0.f);
            G1[(o0 + 1) * 36 + p0 + t + 1] = fmaxf(p01.y, 0.f);
            G1[(o0 + 2) * 36 + p0 + t + 1] = fmaxf(p23.x, 0.f);
            G1[(o0 + 3) * 36 + p0 + t + 1] = fmaxf(p23.y, 0.f);
        }
    }
    __syncthreads();

    // convT2: G1 [64][32] s2 p1 k4 -> G2 [64][64], ReLU.  2o x 8t, f32x2, staged chunks
    {
        const int oo = (tid & 31) * 2;
        const int tt0 = (tid >> 5) * 8;
        u64 ap[8];
        #pragma unroll
        for (int ch = 0; ch < 4; ch++) {
            __syncthreads();
            const float4* src = (const float4*)(g_wt + GW_DW2T + ch * 4352);
            for (int i = tid; i < 1088; i += 256) ((float4*)WT)[i] = src[i];
            __syncthreads();
            if (ch == 0) {
                u64 bb = pk2(__ldg(&db2[oo]), __ldg(&db2[oo + 1]));
                #pragma unroll
                for (int t = 0; t < 8; t++) ap[t] = bb;
            }
            for (int cl = 0; cl < 16; cl++) {
                const float* xr = &G1[(ch * 16 + cl) * 36 + (tt0 >> 1)];
                float4 v = *(const float4*)xr;
                float2 v2 = *(const float2*)(xr + 4);
                u64 xp[6];
                xp[0]=pk(v.x); xp[1]=pk(v.y); xp[2]=pk(v.z); xp[3]=pk(v.w);
                xp[4]=pk(v2.x); xp[5]=pk(v2.y);
                const float* wb = &WT[(cl * 4) * 68 + oo];
                u64 w0 = *(const u64*)(wb);
                u64 w1 = *(const u64*)(wb + 68);
                u64 w2 = *(const u64*)(wb + 136);
                u64 w3 = *(const u64*)(wb + 204);
                #pragma unroll
                for (int t = 0; t < 8; t++) {
                    int u1 = ((t + 1) >> 1) + 1;
                    if (t & 1) {
                        fma2(ap[t], w0, xp[u1]);
                        fma2(ap[t], w2, xp[u1 - 1]);
                    } else {
                        fma2(ap[t], w1, xp[u1]);
                        fma2(ap[t], w3, xp[u1 - 1]);
                    }
                }
            }
        }
        __syncthreads();
        #pragma unroll
        for (int t = 0; t < 8; t++) {
            float2 p = upk(ap[t]);
            G2[oo * 68 + tt0 + t + 1]       = fmaxf(p.x, 0.f);
            G2[(oo + 1) * 68 + tt0 + t + 1] = fmaxf(p.y, 0.f);
        }
    }
    __syncthreads();

    // convT3: G2 [64][64] s2 p1 k4 -> G3 [32][128] (aliases G1).  2o x 8t, f32x2, staged chunks
    {
        const int oo = (tid & 15) * 2;
        const int tt0 = (tid >> 4) * 8;
        u64 ap[8];
        #pragma unroll
        for (int ch = 0; ch < 2; ch++) {
            __syncthreads();
            const float4* src = (const float4*)(g_wt + GW_DW3T + ch * 4352);
            for (int i = tid; i < 1088; i += 256) ((float4*)WT)[i] = src[i];
            __syncthreads();
            if (ch == 0) {
                u64 bb = pk2(__ldg(&db3[oo]), __ldg(&db3[oo + 1]));
                #pragma unroll
                for (int t = 0; t < 8; t++) ap[t] = bb;
            }
            for (int cl = 0; cl < 32; cl++) {
                const float* xr = &G2[(ch * 32 + cl) * 68 + (tt0 >> 1)];
                float4 v = *(const float4*)xr;
                float2 v2 = *(const float2*)(xr + 4);
                u64 xp[6];
                xp[0]=pk(v.x); xp[1]=pk(v.y); xp[2]=pk(v.z); xp[3]=pk(v.w);
                xp[4]=pk(v2.x); xp[5]=pk(v2.y);
                const float* wb = &WT[(cl * 4) * 34 + oo];
                u64 w0 = *(const u64*)(wb);
                u64 w1 = *(const u64*)(wb + 34);
                u64 w2 = *(const u64*)(wb + 68);
                u64 w3 = *(const u64*)(wb + 102);
                #pragma unroll
                for (int t = 0; t < 8; t++) {
                    int u1 = ((t + 1) >> 1) + 1;
                    if (t & 1) {
                        fma2(ap[t], w0, xp[u1]);
                        fma2(ap[t], w2, xp[u1 - 1]);
                    } else {
                        fma2(ap[t], w1, xp[u1]);
                        fma2(ap[t], w3, xp[u1 - 1]);
                    }
                }
            }
        }
        __syncthreads();   // all G1 reads done before aliased G3 writes
        #pragma unroll
        for (int t = 0; t < 8; t++) {
            float2 p = upk(ap[t]);
            G3[oo * 132 + tt0 + t]       = p.x;
            G3[(oo + 1) * 132 + tt0 + t] = p.y;
        }
    }
    __syncthreads();

    // final GEMM: logits[l][v] = sum_e G3[e][l] * ow[v*32+e] + ob[v].  4v x 8l x2, f32x2
    {
        const float4* src = (const float4*)(g_wt + GW_OWT);
        for (int i = tid; i < 1056; i += 256) ((float4*)WT)[i] = src[i];
        __syncthreads();
        const int v0 = (tid & 31) * 4;
        const int l0 = (tid >> 5) * 16;
        u64 b01 = pk2(__ldg(&ob[v0]), __ldg(&ob[v0 + 1]));
        u64 b23 = pk2(__ldg(&ob[v0 + 2]), __ldg(&ob[v0 + 3]));
        #pragma unroll
        for (int lh = 0; lh < 2; lh++) {
            const int l = l0 + lh * 8;
            u64 g01[8], g23[8];
            #pragma unroll
            for (int u = 0; u < 8; u++) { g01[u] = b01; g23[u] = b23; }
            for (int e = 0; e < 32; e++) {
                const float* xr = &G3[e * 132 + l];
                float4 va = *(const float4*)xr;
                float4 vb = *(const float4*)(xr + 4);
                u64 xp[8];
                xp[0]=pk(va.x); xp[1]=pk(va.y); xp[2]=pk(va.z); xp[3]=pk(va.w);
                xp[4]=pk(vb.x); xp[5]=pk(vb.y); xp[6]=pk(vb.z); xp[7]=pk(vb.w);
                const u64* wp = (const u64*)&WT[e * 132 + v0];
                u64 w01 = wp[0], w23 = wp[1];
                #pragma unroll
                for (int u = 0; u < 8; u++) {
                    fma2(g01[u], w01, xp[u]);
                    fma2(g23[u], w23, xp[u]);
                }
            }
            float* outp = out_logits + ((size_t)b * 128 + l) * 128 + v0;
            #pragma unroll
            for (int u = 0; u < 8; u++) {
                float2 p01 = upk(g01[u]), p23 = upk(g23[u]);
                float4 vv = make_float4(p01.x, p01.y, p23.x, p23.y);
                __stcs((float4*)(outp + (size_t)u * 128), vv);
            }
        }
    }
}

// Deterministic loss reduce
__global__ void loss_kernel(float* __restrict__ out_loss)
{
    __shared__ float sm[256];
    float a = 0.f;
    for (int i = threadIdx.x; i < BB; i += 256) a += g_partial[i];
    sm[threadIdx.x] = a;
    __syncthreads();
    for (int sft = 128; sft > 0; sft >>= 1) {
        if (threadIdx.x < sft) sm[threadIdx.x] += sm[threadIdx.x + sft];
        __syncthreads();
    }
    if (threadIdx.x == 0)
        out_loss[0] = sm[0] * (1.25f / (2048.f * 30.f * 64.f));
}

extern "C" void kernel_launch(void* const* d_in, const int* in_sizes, int n_in,
                              void* d_out, int out_size)
{
    const int*   ti     = (const int*)  d_in[0];
    const float* emb    = (const float*)d_in[1];
    const float* enc_w1 = (const float*)d_in[2];
    const float* enc_b1 = (const float*)d_in[3];
    const float* enc_w2 = (const float*)d_in[4];
    const float* enc_b2 = (const float*)d_in[5];
    const float* enc_w3 = (const float*)d_in[6];
    const float* enc_b3 = (const float*)d_in[7];
    const float* cb     = (const float*)d_in[8];
    const float* dec_w1 = (const float*)d_in[9];
    const float* dec_b1 = (const float*)d_in[10];
    const float* dec_w2 = (const float*)d_in[11];
    const float* dec_b2 = (const float*)d_in[12];
    const float* dec_w3 = (const float*)d_in[13];
    const float* dec_b3 = (const float*)d_in[14];
    const float* out_w  = (const float*)d_in[15];
    const float* out_b  = (const float*)d_in[16];

    float* out        = (float*)d_out;
    float* out_logits = out;
    float* out_puzz   = out + OFF_PUZZ;
    float* out_feat   = out + OFF_FEAT;
    float* out_qst    = out + OFF_QST;
    float* out_loss   = out + OFF_LOSS;

    cudaFuncSetAttribute(fused_kernel, cudaFuncAttributeMaxDynamicSharedMemorySize, SM_BYTES);

    prep_kernel<<<64, 256>>>(enc_w1, enc_w2, enc_w3, dec_w1, dec_w2, dec_w3, out_w, emb, cb);
    fused_kernel<<<BB, 256, SM_BYTES>>>(ti, enc_b1, enc_b2, enc_b3, cb,
                                        dec_b1, dec_b2, dec_b3, out_b,
                                        out_logits, out_feat, out_qst, out_puzz);
    loss_kernel<<<1, 256>>>(out_loss);
}

// round 12
// speedup vs baseline: 1.2490x; 1.0053x over previous
#include <cuda_runtime.h>
#include <cstdint>

typedef unsigned long long u64;

__device__ __forceinline__ u64 pk(float x) {
    u64 r; asm("mov.b64 %0, {%1, %1};" : "=l"(r) : "f"(x)); return r;
}
__device__ __forceinline__ u64 pk2(float x, float y) {
    u64 r; asm("mov.b64 %0, {%1, %2};" : "=l"(r) : "f"(x), "f"(y)); return r;
}
__device__ __forceinline__ void fma2(u64& d, u64 a, u64 b) {
    asm("fma.rn.f32x2 %0, %1, %2, %0;" : "+l"(d) : "l"(a), "l"(b));
}
__device__ __forceinline__ void add2(u64& d, u64 a) {
    asm("add.rn.f32x2 %0, %1, %0;" : "+l"(d) : "l"(a));
}
__device__ __forceinline__ float2 upk(u64 v) {
    float2 r; asm("mov.b64 {%0, %1}, %2;" : "=f"(r.x), "=f"(r.y) : "l"(v)); return r;
}

// Problem constants
#define BB   2048
#define LL   128

// Output layout (concatenated, float32)
#define OFF_PUZZ  33554432
#define OFF_FEAT  35397632
#define OFF_QST   153362432
#define OFF_LOSS  271327232

// Scratch
__device__ float g_partial[BB];

// Pre-transposed weights + tables
#define GW_W2T   0
#define GW_W3T   13056
#define GW_DW2T  26112
#define GW_DW3T  43520
#define GW_OWT   52224
#define GW_T1    56448
#define GW_M1    82764
__device__ __align__(16) float g_wt[85008];

__global__ void prep_kernel(const float* __restrict__ w1, const float* __restrict__ w2,
                            const float* __restrict__ w3, const float* __restrict__ dw1,
                            const float* __restrict__ dw2, const float* __restrict__ dw3,
                            const float* __restrict__ ow, const float* __restrict__ emb,
                            const float* __restrict__ cb)
{
    const int tid = blockIdx.x * blockDim.x + threadIdx.x;
    const int nt  = gridDim.x * blockDim.x;
    for (int i = tid; i < 12288; i += nt) {
        int o = i / 192, r = i - o * 192;
        g_wt[GW_W2T + r * 68 + o] = w2[i];
    }
    for (int i = tid; i < 12288; i += nt) {
        int o = i / 192, r = i - o * 192;
        g_wt[GW_W3T + r * 68 + o] = w3[i];
    }
    for (int i = tid; i < 16384; i += nt) {
        int q = i >> 6, o = i & 63;
        g_wt[GW_DW2T + q * 68 + o] = dw2[(q >> 2) * 256 + o * 4 + (q & 3)];
    }
    for (int i = tid; i < 8192; i += nt) {
        int q = i >> 5, o = i & 31;
        g_wt[GW_DW3T + q * 34 + o] = dw3[(q >> 2) * 128 + o * 4 + (q & 3)];
    }
    for (int i = tid; i < 4096; i += nt) {
        int v = i >> 5, e = i & 31;
        g_wt[GW_OWT + e * 132 + v] = ow[i];
    }
    // T1[k][v][o] = sum_e w1[o][e][k] * emb[v][e]; slot v=128 zeros
    for (int idx = tid; idx < 3 * 129 * 64; idx += nt) {
        int o = idx & 63;
        int q = idx >> 6;
        int k = q / 129, v = q - k * 129;
        float acc = 0.f;
        if (v < 128) {
            for (int e = 0; e < 32; e++)
                acc += w1[o * 96 + e * 3 + k] * emb[v * 32 + e];
        }
        g_wt[GW_T1 + q * 68 + o] = acc;
    }
    // M1[k][cd][o] = sum_c dw1[c][o][k] * cb[cd][c]; slot cd=10 zeros.  stride 64
    for (int idx = tid; idx < 3 * 11 * 64; idx += nt) {
        int o = idx & 63;
        int q = idx >> 6;
        int k = q / 11, cd = q - k * 11;
        float acc = 0.f;
        if (cd < 10) {
            for (int c = 0; c < 64; c++)
                acc += dw1[c * 192 + o * 3 + k] * cb[cd * 64 + c];
        }
        g_wt[GW_M1 + q * 64 + o] = acc;
    }
}

// ---------------- Fused shared layout (floats) ----------------
// A (4608) @0    : enc: H2[64][34]@0 + ENC[30][64]@2176
//                  dec: G1[64][36]@0 -> G3[32][132]@0
// B (4352) @4608 : enc: H1[64][68]  dec: G2[64][68]
// WT (4352=2x2176) @8960 ; CB (640) @13312 ; DIST (304) @13952
#define SM_A     0
#define SM_B     4608
#define SM_WT    8960
#define SM_CB    13312
#define SM_DIST  13952
#define SM_FLOATS 14256
#define SM_BYTES  (SM_FLOATS * 4)

#define A_H2   0
#define A_ENC  2176
#define A_G1   0
#define A_G3   0

__global__ void __launch_bounds__(256, 4)
fused_kernel(const int* __restrict__ ti,
             const float* __restrict__ b1, const float* __restrict__ b2,
             const float* __restrict__ b3, const float* __restrict__ cb,
             const float* __restrict__ db1, const float* __restrict__ db2,
             const float* __restrict__ db3, const float* __restrict__ ob,
             float* __restrict__ out_logits,
             float* __restrict__ out_feat, float* __restrict__ out_qst,
             float* __restrict__ out_puzz)
{
    extern __shared__ float s[];
    float* H1  = s + SM_B;
    float* WT  = s + SM_WT;
    float* CB  = s + SM_CB;
    float* DIST= s + SM_DIST;
    float* H2  = s + SM_A + A_H2;
    float* ENC = s + SM_A + A_ENC;
    float* G1  = s + SM_A + A_G1;
    float* G2  = s + SM_B;
    float* G3  = s + SM_A + A_G3;
    __shared__ int   codes_s[30];
    __shared__ float mind_s[30];
    __shared__ int   tok_s[129];

    const int tid = threadIdx.x;
    const int b   = blockIdx.x;

    // ================= ENCODER init =================
    if (tid < 64) H1[tid * 68] = 0.f;          // only col-0 halo needed
    for (int i = tid; i < 640; i += 256) CB[i] = cb[i];
    if (tid < 129) tok_s[tid] = (tid == 0) ? 128 : __ldg(&ti[b * LL + tid - 1]);
    // stage conv2 chunk0 into buf0
    {
        const float4* sp = (const float4*)(g_wt + GW_W2T);
        for (int i = tid; i < 408; i += 256) ((float4*)WT)[i] = __ldg(&sp[i]);
    }
    __syncthreads();

    // conv1 via T1 table: H1[o][t+1] = relu(b1[o] + sum_k T1[k][tok[2t+k]][o]).  4o x 4t
    {
        const int o0 = (tid & 15) * 4;
        const int t0 = (tid >> 4) * 4;
        u64 a01[4], a23[4];
        {
            u64 bb01 = pk2(__ldg(&b1[o0]), __ldg(&b1[o0 + 1]));
            u64 bb23 = pk2(__ldg(&b1[o0 + 2]), __ldg(&b1[o0 + 3]));
            #pragma unroll
            for (int t = 0; t < 4; t++) { a01[t] = bb01; a23[t] = bb23; }
        }
        int tk[9];
        #pragma unroll
        for (int u = 0; u < 9; u++) tk[u] = tok_s[2 * t0 + u];
        #pragma unroll
        for (int k = 0; k < 3; k++) {
            #pragma unroll
            for (int t = 0; t < 4; t++) {
                const u64* p = (const u64*)(g_wt + GW_T1 + (k * 129 + tk[2 * t + k]) * 68 + o0);
                add2(a01[t], __ldg(p));
                add2(a23[t], __ldg(p + 1));
            }
        }
        #pragma unroll
        for (int t = 0; t < 4; t++) {
            float2 p01 = upk(a01[t]), p23 = upk(a23[t]);
            H1[(o0 + 0) * 68 + t0 + t + 1] = fmaxf(p01.x, 0.f);
            H1[(o0 + 1) * 68 + t0 + t + 1] = fmaxf(p01.y, 0.f);
            H1[(o0 + 2) * 68 + t0 + t + 1] = fmaxf(p23.x, 0.f);
            H1[(o0 + 3) * 68 + t0 + t + 1] = fmaxf(p23.y, 0.f);
        }
    }
    __syncthreads();

    // conv2: H1 [64][64] pad1 s2 k3 -> H2 [64][32] (stride 34), ReLU.
    // 4o x 2t, f32x2, double-buffered chunks of 8 e (408 f4 each)
    {
        const int o0 = (tid & 15) * 4;
        const int t0 = (tid >> 4) * 2;
        u64 a01[2], a23[2];
        {
            u64 bb01 = pk2(__ldg(&b2[o0]), __ldg(&b2[o0 + 1]));
            u64 bb23 = pk2(__ldg(&b2[o0 + 2]), __ldg(&b2[o0 + 3]));
            a01[0] = a01[1] = bb01;
            a23[0] = a23[1] = bb23;
        }
        const float4* wsrc = (const float4*)(g_wt + GW_W2T);
        #pragma unroll 1
        for (int ch = 0; ch < 8; ch++) {
            float4 pre[2];
            if (ch < 7) {
                const float4* sp = wsrc + (ch + 1) * 408;
                #pragma unroll
                for (int j = 0; j < 2; j++) {
                    int i = tid + j * 256;
                    if (i < 408) pre[j] = __ldg(&sp[i]);
                }
            }
            const float* cur = WT + (ch & 1) * 2176;
            for (int el = 0; el < 8; el++) {
                const float* xr = &H1[(ch * 8 + el) * 68 + 2 * t0];
                float4 v = *(const float4*)xr;
                float x4 = xr[4];
                u64 xp[5];
                xp[0]=pk(v.x); xp[1]=pk(v.y); xp[2]=pk(v.z); xp[3]=pk(v.w); xp[4]=pk(x4);
                #pragma unroll
                for (int k = 0; k < 3; k++) {
                    const u64* wp = (const u64*)&cur[(el * 3 + k) * 68 + o0];
                    u64 w01 = wp[0], w23 = wp[1];
                    #pragma unroll
                    for (int t = 0; t < 2; t++) {
                        fma2(a01[t], w01, xp[2 * t + k]);
                        fma2(a23[t], w23, xp[2 * t + k]);
                    }
                }
            }
            if (ch < 7) {
                float4* dp = (float4*)(WT + ((ch + 1) & 1) * 2176);
                #pragma unroll
                for (int j = 0; j < 2; j++) {
                    int i = tid + j * 256;
                    if (i < 408) dp[i] = pre[j];
                }
            }
            __syncthreads();
        }
        // epilogue: store H2 + stage conv3 chunk0 into buf0
        #pragma unroll
        for (int t = 0; t < 2; t++) {
            float2 p01 = upk(a01[t]), p23 = upk(a23[t]);
            H2[(o0 + 0) * 34 + t0 + t] = fmaxf(p01.x, 0.f);
            H2[(o0 + 1) * 34 + t0 + t] = fmaxf(p01.y, 0.f);
            H2[(o0 + 2) * 34 + t0 + t] = fmaxf(p23.x, 0.f);
            H2[(o0 + 3) * 34 + t0 + t] = fmaxf(p23.y, 0.f);
        }
        {
            const float4* sp = (const float4*)(g_wt + GW_W3T);
            for (int i = tid; i < 408; i += 256) ((float4*)WT)[i] = __ldg(&sp[i]);
        }
        __syncthreads();
    }

    // conv3: H2 [64][32] pad0 s1 k3 -> ENC [30][64] transposed.
    // 2o x 5t, 192 act; double-buffered chunks of 8 e
    {
        const bool act = tid < 192;
        const int o0 = (tid & 31) * 2;
        const int t0 = (tid >> 5) * 5;
        u64 ap[5];
        if (act) {
            u64 bb = pk2(__ldg(&b3[o0]), __ldg(&b3[o0 + 1]));
            #pragma unroll
            for (int t = 0; t < 5; t++) ap[t] = bb;
        }
        const float4* wsrc = (const float4*)(g_wt + GW_W3T);
        #pragma unroll 1
        for (int ch = 0; ch < 8; ch++) {
            float4 pre[2];
            if (ch < 7) {
                const float4* sp = wsrc + (ch + 1) * 408;
                #pragma unroll
                for (int j = 0; j < 2; j++) {
                    int i = tid + j * 256;
                    if (i < 408) pre[j] = __ldg(&sp[i]);
                }
            }
            const float* cur = WT + (ch & 1) * 2176;
            if (act) {
                for (int el = 0; el < 8; el++) {
                    const float* xr = &H2[(ch * 8 + el) * 34 + t0];
                    u64 xp[7];
                    #pragma unroll
                    for (int u = 0; u < 7; u++) xp[u] = pk(xr[u]);
                    #pragma unroll
                    for (int k = 0; k < 3; k++) {
                        u64 w = *(const u64*)&cur[(el * 3 + k) * 68 + o0];
                        #pragma unroll
                        for (int t = 0; t < 5; t++) fma2(ap[t], w, xp[t + k]);
                    }
                }
            }
            if (ch < 7) {
                float4* dp = (float4*)(WT + ((ch + 1) & 1) * 2176);
                #pragma unroll
                for (int j = 0; j < 2; j++) {
                    int i = tid + j * 256;
                    if (i < 408) dp[i] = pre[j];
                }
            }
            __syncthreads();
        }
        if (act) {
            #pragma unroll
            for (int t = 0; t < 5; t++) {
                float2 p = upk(ap[t]);
                ENC[(t0 + t) * 64 + o0]     = p.x;
                ENC[(t0 + t) * 64 + o0 + 1] = p.y;
            }
        }
    }
    __syncthreads();

    // VQ distances + argmin
    for (int idx = tid; idx < 300; idx += 256) {
        int i = idx / 10, c = idx - i * 10;
        const float* fe = &ENC[i * 64];
        const float* cc = &CB[c * 64];
        float acc = 0.f;
        #pragma unroll 8
        for (int d = 0; d < 64; d++) { float df = fe[d] - cc[d]; acc += df * df; }
        DIST[i * 10 + c] = acc;
    }
    __syncthreads();
    if (tid < 30) {
        float mv = DIST[tid * 10]; int mc = 0;
        #pragma unroll
        for (int c = 1; c < 10; c++) {
            float v = DIST[tid * 10 + c];
            if (v < mv) { mv = v; mc = c; }
        }
        codes_s[tid] = mc;
        mind_s[tid] = mv;
    }
    __syncthreads();
    if (tid == 0) {
        float acc = 0.f;
        #pragma unroll
        for (int i = 0; i < 30; i++) acc += mind_s[i];
        g_partial[b] = acc;
    }

    // ---- broadcast stores (register-cached, streaming) ----
    {
        float* puz = out_puzz + (size_t)b * 900;
        for (int idx = tid; idx < 900; idx += 256)
            __stcs(&puz[idx], (float)codes_s[idx / 30]);

        const float4* enc4 = (const float4*)ENC;
        const float4* cb4  = (const float4*)CB;
        float4* f4 = (float4*)out_feat + (size_t)b * 14400;
        float4* q4 = (float4*)out_qst  + (size_t)b * 14400;
        const int lane = tid & 31;
        const int wid  = tid >> 5;
        const int q    = lane & 15;
        const int jh   = lane >> 4;
        for (int i = wid; i < 30; i += 8) {
            float4 ev = enc4[i * 16 + q];
            float4 cv = cb4[codes_s[i] * 16 + q];
            float4* fb = f4 + i * 480 + jh * 16 + q;
            float4* qb = q4 + i * 480 + jh * 16 + q;
            #pragma unroll
            for (int j = 0; j < 30; j += 2) {
                __stcs(fb + j * 16, ev);
                __stcs(qb + j * 16, cv);
            }
        }
    }
    __syncthreads();

    // ================= DECODER init =================
    // halo zeros only; stage M1 (stride 64, 2112 floats) into buf1
    if (tid < 64) {
        G1[tid * 36]      = 0.f;
        G1[tid * 36 + 33] = 0.f;
        G2[tid * 68]      = 0.f;
        G2[tid * 68 + 65] = 0.f;
    }
    {
        const float4* sp = (const float4*)(g_wt + GW_M1);
        float4* dp = (float4*)(WT + 2176);
        for (int i = tid; i < 528; i += 256) dp[i] = __ldg(&sp[i]);
    }
    __syncthreads();

    // convT1 via M1 table (threads<128); threads>=128 stage convT2 chunk0 into buf0
    if (tid < 128) {
        const float* WTM = WT + 2176;
        const int o0 = (tid & 15) * 4;
        const int p0 = (tid >> 4) * 4;
        u64 a01[4], a23[4];
        {
            u64 bb01 = pk2(__ldg(&db1[o0]), __ldg(&db1[o0 + 1]));
            u64 bb23 = pk2(__ldg(&db1[o0 + 2]), __ldg(&db1[o0 + 3]));
            #pragma unroll
            for (int t = 0; t < 4; t++) { a01[t] = bb01; a23[t] = bb23; }
        }
        #pragma unroll
        for (int k = 0; k < 3; k++) {
            #pragma unroll
            for (int t = 0; t < 4; t++) {
                int i = p0 + t - k;
                int cd = ((unsigned)i < 30u) ? codes_s[i] : 10;
                const u64* mp = (const u64*)&WTM[(k * 11 + cd) * 64 + o0];
                add2(a01[t], mp[0]);
                add2(a23[t], mp[1]);
            }
        }
        #pragma unroll
        for (int t = 0; t < 4; t++) {
            float2 p01 = upk(a01[t]), p23 = upk(a23[t]);
            G1[(o0 + 0) * 36 + p0 + t + 1] = fmaxf(p01.x, 0.f);
            G1[(o0 + 1) * 36 + p0 + t + 1] = fmaxf(p01.y, 0.f);
            G1[(o0 + 2) * 36 + p0 + t + 1] = fmaxf(p23.x, 0.f);
            G1[(o0 + 3) * 36 + p0 + t + 1] = fmaxf(p23.y, 0.f);
        }
    } else {
        const float4* sp = (const float4*)(g_wt + GW_DW2T);
        float4* dp = (float4*)WT;
        for (int i = tid - 128; i < 544; i += 128) dp[i] = __ldg(&sp[i]);
    }
    __syncthreads();

    // convT2: G1 [64][32] s2 p1 k4 -> G2 [64][64], ReLU.
    // 2o x 8t, f32x2, double-buffered chunks of 8 cl (544 f4 each)
    {
        const int oo = (tid & 31) * 2;
        const int tt0 = (tid >> 5) * 8;
        u64 ap[8];
        {
            u64 bb = pk2(__ldg(&db2[oo]), __ldg(&db2[oo + 1]));
            #pragma unroll
            for (int t = 0; t < 8; t++) ap[t] = bb;
        }
        const float4* wsrc = (const float4*)(g_wt + GW_DW2T);
        #pragma unroll 1
        for (int ch = 0; ch < 8; ch++) {
            float4 pre[3];
            if (ch < 7) {
                const float4* sp = wsrc + (ch + 1) * 544;
                #pragma unroll
                for (int j = 0; j < 3; j++) {
                    int i = tid + j * 256;
                    if (i < 544) pre[j] = __ldg(&sp[i]);
                }
            }
            const float* cur = WT + (ch & 1) * 2176;
            for (int cl = 0; cl < 8; cl++) {
                const float* xr = &G1[(ch * 8 + cl) * 36 + (tt0 >> 1)];
                float4 v = *(const float4*)xr;
                float2 v2 = *(const float2*)(xr + 4);
                u64 xp[6];
                xp[0]=pk(v.x); xp[1]=pk(v.y); xp[2]=pk(v.z); xp[3]=pk(v.w);
                xp[4]=pk(v2.x); xp[5]=pk(v2.y);
                const float* wb = &cur[(cl * 4) * 68 + oo];
                u64 w0 = *(const u64*)(wb);
                u64 w1 = *(const u64*)(wb + 68);
                u64 w2 = *(const u64*)(wb + 136);
                u64 w3 = *(const u64*)(wb + 204);
                #pragma unroll
                for (int t = 0; t < 8; t++) {
                    int u1 = ((t + 1) >> 1) + 1;
                    if (t & 1) {
                        fma2(ap[t], w0, xp[u1]);
                        fma2(ap[t], w2, xp[u1 - 1]);
                    } else {
                        fma2(ap[t], w1, xp[u1]);
                        fma2(ap[t], w3, xp[u1 - 1]);
                    }
                }
            }
            if (ch < 7) {
                float4* dp = (float4*)(WT + ((ch + 1) & 1) * 2176);
                #pragma unroll
                for (int j = 0; j < 3; j++) {
                    int i = tid + j * 256;
                    if (i < 544) dp[i] = pre[j];
                }
            }
            __syncthreads();
        }
        // epilogue: store G2 + stage convT3 chunk0 into buf0
        #pragma unroll
        for (int t = 0; t < 8; t++) {
            float2 p = upk(ap[t]);
            G2[oo * 68 + tt0 + t + 1]       = fmaxf(p.x, 0.f);
            G2[(oo + 1) * 68 + tt0 + t + 1] = fmaxf(p.y, 0.f);
        }
        {
            const float4* sp = (const float4*)(g_wt + GW_DW3T);
            for (int i = tid; i < 272; i += 256) ((float4*)WT)[i] = __ldg(&sp[i]);
        }
        __syncthreads();
    }

    // convT3: G2 [64][64] s2 p1 k4 -> G3 [32][128] (aliases G1).
    // 2o x 8t, f32x2, double-buffered chunks of 8 cl (272 f4 each)
    {
        const int oo = (tid & 15) * 2;
        const int tt0 = (tid >> 4) * 8;
        u64 ap[8];
        {
            u64 bb = pk2(__ldg(&db3[oo]), __ldg(&db3[oo + 1]));
            #pragma unroll
            for (int t = 0; t < 8; t++) ap[t] = bb;
        }
        const float4* wsrc = (const float4*)(g_wt + GW_DW3T);
        #pragma unroll 1
        for (int ch = 0; ch < 8; ch++) {
            float4 pre[2];
            if (ch < 7) {
                const float4* sp = wsrc + (ch + 1) * 272;
                #pragma unroll
                for (int j = 0; j < 2; j++) {
                    int i = tid + j * 256;
                    if (i < 272) pre[j] = __ldg(&sp[i]);
                }
            }
            const float* cur = WT + (ch & 1) * 2176;
            for (int cl = 0; cl < 8; cl++) {
                const float* xr = &G2[(ch * 8 + cl) * 68 + (tt0 >> 1)];
                float4 v = *(const float4*)xr;
                float2 v2 = *(const float2*)(xr + 4);
                u64 xp[6];
                xp[0]=pk(v.x); xp[1]=pk(v.y); xp[2]=pk(v.z); xp[3]=pk(v.w);
                xp[4]=pk(v2.x); xp[5]=pk(v2.y);
                const float* wb = &cur[(cl * 4) * 34 + oo];
                u64 w0 = *(const u64*)(wb);
                u64 w1 = *(const u64*)(wb + 34);
                u64 w2 = *(const u64*)(wb + 68);
                u64 w3 = *(const u64*)(wb + 102);
                #pragma unroll
                for (int t = 0; t < 8; t++) {
                    int u1 = ((t + 1) >> 1) + 1;
                    if (t & 1) {
                        fma2(ap[t], w0, xp[u1]);
                        fma2(ap[t], w2, xp[u1 - 1]);
                    } else {
                        fma2(ap[t], w1, xp[u1]);
                        fma2(ap[t], w3, xp[u1 - 1]);
                    }
                }
            }
            if (ch < 7) {
                float4* dp = (float4*)(WT + ((ch + 1) & 1) * 2176);
                #pragma unroll
                for (int j = 0; j < 2; j++) {
                    int i = tid + j * 256;
                    if (i < 272) dp[i] = pre[j];
                }
            }
            __syncthreads();
        }
        // epilogue: store G3 (aliases G1 region) + stage GEMM weights (full 1056 f4)
        #pragma unroll
        for (int t = 0; t < 8; t++) {
            float2 p = upk(ap[t]);
            G3[oo * 132 + tt0 + t]       = p.x;
            G3[(oo + 1) * 132 + tt0 + t] = p.y;
        }
        {
            const float4* sp = (const float4*)(g_wt + GW_OWT);
            for (int i = tid; i < 1056; i += 256) ((float4*)WT)[i] = __ldg(&sp[i]);
        }
        __syncthreads();
    }

    // final GEMM: logits[l][v] = sum_e G3[e][l] * ow[v*32+e] + ob[v].  4v x 8l x2, f32x2
    {
        const int v0 = (tid & 31) * 4;
        const int l0 = (tid >> 5) * 16;
        u64 b01 = pk2(__ldg(&ob[v0]), __ldg(&ob[v0 + 1]));
        u64 b23 = pk2(__ldg(&ob[v0 + 2]), __ldg(&ob[v0 + 3]));
        #pragma unroll
        for (int lh = 0; lh < 2; lh++) {
            const int l = l0 + lh * 8;
            u64 g01[8], g23[8];
            #pragma unroll
            for (int u = 0; u < 8; u++) { g01[u] = b01; g23[u] = b23; }
            for (int e = 0; e < 32; e++) {
                const float* xr = &G3[e * 132 + l];
                float4 va = *(const float4*)xr;
                float4 vb = *(const float4*)(xr + 4);
                u64 xp[8];
                xp[0]=pk(va.x); xp[1]=pk(va.y); xp[2]=pk(va.z); xp[3]=pk(va.w);
                xp[4]=pk(vb.x); xp[5]=pk(vb.y); xp[6]=pk(vb.z); xp[7]=pk(vb.w);
                const u64* wp = (const u64*)&WT[e * 132 + v0];
                u64 w01 = wp[0], w23 = wp[1];
                #pragma unroll
                for (int u = 0; u < 8; u++) {
                    fma2(g01[u], w01, xp[u]);
                    fma2(g23[u], w23, xp[u]);
                }
            }
            float* outp = out_logits + ((size_t)b * 128 + l) * 128 + v0;
            #pragma unroll
            for (int u = 0; u < 8; u++) {
                float2 p01 = upk(g01[u]), p23 = upk(g23[u]);
                float4 vv = make_float4(p01.x, p01.y, p23.x, p23.y);
                __stcs((float4*)(outp + (size_t)u * 128), vv);
            }
        }
    }
}

// Deterministic loss reduce
__global__ void loss_kernel(float* __restrict__ out_loss)
{
    __shared__ float sm[256];
    float a = 0.f;
    for (int i = threadIdx.x; i < BB; i += 256) a += g_partial[i];
    sm[threadIdx.x] = a;
    __syncthreads();
    for (int sft = 128; sft > 0; sft >>= 1) {
        if (threadIdx.x < sft) sm[threadIdx.x] += sm[threadIdx.x + sft];
        __syncthreads();
    }
    if (threadIdx.x == 0)
        out_loss[0] = sm[0] * (1.25f / (2048.f * 30.f * 64.f));
}

extern "C" void kernel_launch(void* const* d_in, const int* in_sizes, int n_in,
                              void* d_out, int out_size)
{
    const int*   ti     = (const int*)  d_in[0];
    const float* emb    = (const float*)d_in[1];
    const float* enc_w1 = (const float*)d_in[2];
    const float* enc_b1 = (const float*)d_in[3];
    const float* enc_w2 = (const float*)d_in[4];
    const float* enc_b2 = (const float*)d_in[5];
    const float* enc_w3 = (const float*)d_in[6];
    const float* enc_b3 = (const float*)d_in[7];
    const float* cb     = (const float*)d_in[8];
    const float* dec_w1 = (const float*)d_in[9];
    const float* dec_b1 = (const float*)d_in[10];
    const float* dec_w2 = (const float*)d_in[11];
    const float* dec_b2 = (const float*)d_in[12];
    const float* dec_w3 = (const float*)d_in[13];
    const float* dec_b3 = (const float*)d_in[14];
    const float* out_w  = (const float*)d_in[15];
    const float* out_b  = (const float*)d_in[16];

    float* out        = (float*)d_out;
    float* out_logits = out;
    float* out_puzz   = out + OFF_PUZZ;
    float* out_feat   = out + OFF_FEAT;
    float* out_qst    = out + OFF_QST;
    float* out_loss   = out + OFF_LOSS;

    cudaFuncSetAttribute(fused_kernel, cudaFuncAttributeMaxDynamicSharedMemorySize, SM_BYTES);

    prep_kernel<<<64, 256>>>(enc_w1, enc_w2, enc_w3, dec_w1, dec_w2, dec_w3, out_w, emb, cb);
    fused_kernel<<<BB, 256, SM_BYTES>>>(ti, enc_b1, enc_b2, enc_b3, cb,
                                        dec_b1, dec_b2, dec_b3, out_b,
                                        out_logits, out_feat, out_qst, out_puzz);
    loss_kernel<<<1, 256>>>(out_loss);
}

// round 13
// speedup vs baseline: 1.2645x; 1.0124x over previous
#include <cuda_runtime.h>
#include <cstdint>

typedef unsigned long long u64;

__device__ __forceinline__ u64 pk(float x) {
    u64 r; asm("mov.b64 %0, {%1, %1};" : "=l"(r) : "f"(x)); return r;
}
__device__ __forceinline__ u64 pk2(float x, float y) {
    u64 r; asm("mov.b64 %0, {%1, %2};" : "=l"(r) : "f"(x), "f"(y)); return r;
}
__device__ __forceinline__ void fma2(u64& d, u64 a, u64 b) {
    asm("fma.rn.f32x2 %0, %1, %2, %0;" : "+l"(d) : "l"(a), "l"(b));
}
__device__ __forceinline__ void add2(u64& d, u64 a) {
    asm("add.rn.f32x2 %0, %1, %0;" : "+l"(d) : "l"(a));
}
__device__ __forceinline__ float2 upk(u64 v) {
    float2 r; asm("mov.b64 {%0, %1}, %2;" : "=f"(r.x), "=f"(r.y) : "l"(v)); return r;
}

// Problem constants
#define BB   2048
#define LL   128

// Output layout (concatenated, float32)
#define OFF_PUZZ  33554432
#define OFF_FEAT  35397632
#define OFF_QST   153362432
#define OFF_LOSS  271327232

// Scratch
__device__ float g_partial[BB];

// Pre-transposed weights + tables
#define GW_W2T   0
#define GW_W3T   13056
#define GW_DW2T  26112
#define GW_DW3T  43520
#define GW_OWT   52224
#define GW_T1    56448
#define GW_M1    82764
__device__ __align__(16) float g_wt[85008];

__global__ void prep_kernel(const float* __restrict__ w1, const float* __restrict__ w2,
                            const float* __restrict__ w3, const float* __restrict__ dw1,
                            const float* __restrict__ dw2, const float* __restrict__ dw3,
                            const float* __restrict__ ow, const float* __restrict__ emb,
                            const float* __restrict__ cb)
{
    const int tid = blockIdx.x * blockDim.x + threadIdx.x;
    const int nt  = gridDim.x * blockDim.x;
    for (int i = tid; i < 12288; i += nt) {
        int o = i / 192, r = i - o * 192;
        g_wt[GW_W2T + r * 68 + o] = w2[i];
    }
    for (int i = tid; i < 12288; i += nt) {
        int o = i / 192, r = i - o * 192;
        g_wt[GW_W3T + r * 68 + o] = w3[i];
    }
    for (int i = tid; i < 16384; i += nt) {
        int q = i >> 6, o = i & 63;
        g_wt[GW_DW2T + q * 68 + o] = dw2[(q >> 2) * 256 + o * 4 + (q & 3)];
    }
    for (int i = tid; i < 8192; i += nt) {
        int q = i >> 5, o = i & 31;
        g_wt[GW_DW3T + q * 34 + o] = dw3[(q >> 2) * 128 + o * 4 + (q & 3)];
    }
    for (int i = tid; i < 4096; i += nt) {
        int v = i >> 5, e = i & 31;
        g_wt[GW_OWT + e * 132 + v] = ow[i];
    }
    // T1[k][v][o] = sum_e w1[o][e][k] * emb[v][e]; slot v=128 zeros
    for (int idx = tid; idx < 3 * 129 * 64; idx += nt) {
        int o = idx & 63;
        int q = idx >> 6;
        int k = q / 129, v = q - k * 129;
        float acc = 0.f;
        if (v < 128) {
            for (int e = 0; e < 32; e++)
                acc += w1[o * 96 + e * 3 + k] * emb[v * 32 + e];
        }
        g_wt[GW_T1 + q * 68 + o] = acc;
    }
    // M1[k][cd][o] = sum_c dw1[c][o][k] * cb[cd][c]; slot cd=10 zeros.  stride 64
    for (int idx = tid; idx < 3 * 11 * 64; idx += nt) {
        int o = idx & 63;
        int q = idx >> 6;
        int k = q / 11, cd = q - k * 11;
        float acc = 0.f;
        if (cd < 10) {
            for (int c = 0; c < 64; c++)
                acc += dw1[c * 192 + o * 3 + k] * cb[cd * 64 + c];
        }
        g_wt[GW_M1 + q * 64 + o] = acc;
    }
}

// ---------------- Fused shared layout (floats) ----------------
// A (4608) @0    : enc: H2[64][34]@0 + ENC[30][64]@2176
//                  dec: G1[64][36]@0 -> G3[32][132]@0
// B (4352) @4608 : enc: H1[64][68]  dec: G2[64][68]
// WT (2176 = 2x1088) @8960 ; CB (640) @11136 ; DIST (304) @11776
#define SM_A     0
#define SM_B     4608
#define SM_WT    8960
#define SM_CB    11136
#define SM_DIST  11776
#define SM_FLOATS 12080
#define SM_BYTES  (SM_FLOATS * 4)

#define A_H2   0
#define A_ENC  2176
#define A_G1   0
#define A_G3   0

__global__ void __launch_bounds__(256, 4)
fused_kernel(const int* __restrict__ ti,
             const float* __restrict__ b1, const float* __restrict__ b2,
             const float* __restrict__ b3, const float* __restrict__ cb,
             const float* __restrict__ db1, const float* __restrict__ db2,
             const float* __restrict__ db3, const float* __restrict__ ob,
             float* __restrict__ out_logits,
             float* __restrict__ out_feat, float* __restrict__ out_qst,
             float* __restrict__ out_puzz)
{
    extern __shared__ float s[];
    float* H1  = s + SM_B;
    float* WT  = s + SM_WT;
    float* CB  = s + SM_CB;
    float* DIST= s + SM_DIST;
    float* H2  = s + SM_A + A_H2;
    float* ENC = s + SM_A + A_ENC;
    float* G1  = s + SM_A + A_G1;
    float* G2  = s + SM_B;
    float* G3  = s + SM_A + A_G3;
    __shared__ int   codes_s[30];
    __shared__ float mind_s[30];
    __shared__ int   tok_s[129];

    const int tid = threadIdx.x;
    const int b   = blockIdx.x;

    // ================= ENCODER init =================
    if (tid < 64) H1[tid * 68] = 0.f;          // col-0 halo only
    for (int i = tid; i < 640; i += 256) CB[i] = cb[i];
    if (tid < 129) tok_s[tid] = (tid == 0) ? 128 : __ldg(&ti[b * LL + tid - 1]);
    // stage conv2 chunk0 (204 f4) into buf0
    {
        const float4* sp = (const float4*)(g_wt + GW_W2T);
        if (tid < 204) ((float4*)WT)[tid] = __ldg(&sp[tid]);
    }
    __syncthreads();

    // conv1 via T1 table: H1[o][t+1] = relu(b1[o] + sum_k T1[k][tok[2t+k]][o]).  4o x 4t
    {
        const int o0 = (tid & 15) * 4;
        const int t0 = (tid >> 4) * 4;
        u64 a01[4], a23[4];
        {
            u64 bb01 = pk2(__ldg(&b1[o0]), __ldg(&b1[o0 + 1]));
            u64 bb23 = pk2(__ldg(&b1[o0 + 2]), __ldg(&b1[o0 + 3]));
            #pragma unroll
            for (int t = 0; t < 4; t++) { a01[t] = bb01; a23[t] = bb23; }
        }
        int tk[9];
        #pragma unroll
        for (int u = 0; u < 9; u++) tk[u] = tok_s[2 * t0 + u];
        #pragma unroll
        for (int k = 0; k < 3; k++) {
            #pragma unroll
            for (int t = 0; t < 4; t++) {
                const u64* p = (const u64*)(g_wt + GW_T1 + (k * 129 + tk[2 * t + k]) * 68 + o0);
                add2(a01[t], __ldg(p));
                add2(a23[t], __ldg(p + 1));
            }
        }
        #pragma unroll
        for (int t = 0; t < 4; t++) {
            float2 p01 = upk(a01[t]), p23 = upk(a23[t]);
            H1[(o0 + 0) * 68 + t0 + t + 1] = fmaxf(p01.x, 0.f);
            H1[(o0 + 1) * 68 + t0 + t + 1] = fmaxf(p01.y, 0.f);
            H1[(o0 + 2) * 68 + t0 + t + 1] = fmaxf(p23.x, 0.f);
            H1[(o0 + 3) * 68 + t0 + t + 1] = fmaxf(p23.y, 0.f);
        }
    }
    __syncthreads();

    // conv2: H1 [64][64] pad1 s2 k3 -> H2 [64][32] (stride 34), ReLU.
    // 4o x 2t, f32x2, double-buffered chunks of 4 e (204 f4)
    {
        const int o0 = (tid & 15) * 4;
        const int t0 = (tid >> 4) * 2;
        u64 a01[2], a23[2];
        {
            u64 bb01 = pk2(__ldg(&b2[o0]), __ldg(&b2[o0 + 1]));
            u64 bb23 = pk2(__ldg(&b2[o0 + 2]), __ldg(&b2[o0 + 3]));
            a01[0] = a01[1] = bb01;
            a23[0] = a23[1] = bb23;
        }
        const float4* wsrc = (const float4*)(g_wt + GW_W2T);
        #pragma unroll 1
        for (int ch = 0; ch < 16; ch++) {
            float4 pre;
            if (ch < 15 && tid < 204) pre = __ldg(&wsrc[(ch + 1) * 204 + tid]);
            const float* cur = WT + (ch & 1) * 1088;
            for (int el = 0; el < 4; el++) {
                const float* xr = &H1[(ch * 4 + el) * 68 + 2 * t0];
                float4 v = *(const float4*)xr;
                float x4 = xr[4];
                u64 xp[5];
                xp[0]=pk(v.x); xp[1]=pk(v.y); xp[2]=pk(v.z); xp[3]=pk(v.w); xp[4]=pk(x4);
                #pragma unroll
                for (int k = 0; k < 3; k++) {
                    const u64* wp = (const u64*)&cur[(el * 3 + k) * 68 + o0];
                    u64 w01 = wp[0], w23 = wp[1];
                    #pragma unroll
                    for (int t = 0; t < 2; t++) {
                        fma2(a01[t], w01, xp[2 * t + k]);
                        fma2(a23[t], w23, xp[2 * t + k]);
                    }
                }
            }
            if (ch < 15 && tid < 204)
                ((float4*)(WT + ((ch + 1) & 1) * 1088))[tid] = pre;
            __syncthreads();
        }
        // epilogue: store H2 + stage conv3 chunk0
        #pragma unroll
        for (int t = 0; t < 2; t++) {
            float2 p01 = upk(a01[t]), p23 = upk(a23[t]);
            H2[(o0 + 0) * 34 + t0 + t] = fmaxf(p01.x, 0.f);
            H2[(o0 + 1) * 34 + t0 + t] = fmaxf(p01.y, 0.f);
            H2[(o0 + 2) * 34 + t0 + t] = fmaxf(p23.x, 0.f);
            H2[(o0 + 3) * 34 + t0 + t] = fmaxf(p23.y, 0.f);
        }
        {
            const float4* sp = (const float4*)(g_wt + GW_W3T);
            if (tid < 204) ((float4*)WT)[tid] = __ldg(&sp[tid]);
        }
        __syncthreads();
    }

    // conv3: H2 [64][32] pad0 s1 k3 -> ENC [30][64] transposed.
    // 2o x 4t (256 threads, last group 2), double-buffered chunks of 4 e
    {
        const int o0 = (tid & 31) * 2;
        const int t0 = (tid >> 5) * 4;
        u64 ap[4];
        {
            u64 bb = pk2(__ldg(&b3[o0]), __ldg(&b3[o0 + 1]));
            #pragma unroll
            for (int t = 0; t < 4; t++) ap[t] = bb;
        }
        const float4* wsrc = (const float4*)(g_wt + GW_W3T);
        #pragma unroll 1
        for (int ch = 0; ch < 16; ch++) {
            float4 pre;
            if (ch < 15 && tid < 204) pre = __ldg(&wsrc[(ch + 1) * 204 + tid]);
            const float* cur = WT + (ch & 1) * 1088;
            for (int el = 0; el < 4; el++) {
                const float* xr = &H2[(ch * 4 + el) * 34 + t0];
                u64 xp[6];
                #pragma unroll
                for (int u = 0; u < 6; u++) xp[u] = pk(xr[u]);
                #pragma unroll
                for (int k = 0; k < 3; k++) {
                    u64 w = *(const u64*)&cur[(el * 3 + k) * 68 + o0];
                    #pragma unroll
                    for (int t = 0; t < 4; t++) fma2(ap[t], w, xp[t + k]);
                }
            }
            if (ch < 15 && tid < 204)
                ((float4*)(WT + ((ch + 1) & 1) * 1088))[tid] = pre;
            __syncthreads();
        }
        #pragma unroll
        for (int t = 0; t < 4; t++) {
            if (t0 + t < 30) {
                float2 p = upk(ap[t]);
                ENC[(t0 + t) * 64 + o0]     = p.x;
                ENC[(t0 + t) * 64 + o0 + 1] = p.y;
            }
        }
    }
    __syncthreads();

    // VQ distances + argmin
    for (int idx = tid; idx < 300; idx += 256) {
        int i = idx / 10, c = idx - i * 10;
        const float* fe = &ENC[i * 64];
        const float* cc = &CB[c * 64];
        float acc = 0.f;
        #pragma unroll 8
        for (int d = 0; d < 64; d++) { float df = fe[d] - cc[d]; acc += df * df; }
        DIST[i * 10 + c] = acc;
    }
    __syncthreads();
    if (tid < 30) {
        float mv = DIST[tid * 10]; int mc = 0;
        #pragma unroll
        for (int c = 1; c < 10; c++) {
            float v = DIST[tid * 10 + c];
            if (v < mv) { mv = v; mc = c; }
        }
        codes_s[tid] = mc;
        mind_s[tid] = mv;
    }
    __syncthreads();
    if (tid == 0) {
        float acc = 0.f;
        #pragma unroll
        for (int i = 0; i < 30; i++) acc += mind_s[i];
        g_partial[b] = acc;
    }

    // ---- broadcast stores (register-cached, streaming) ----
    {
        float* puz = out_puzz + (size_t)b * 900;
        for (int idx = tid; idx < 900; idx += 256)
            __stcs(&puz[idx], (float)codes_s[idx / 30]);

        const float4* enc4 = (const float4*)ENC;
        const float4* cb4  = (const float4*)CB;
        float4* f4 = (float4*)out_feat + (size_t)b * 14400;
        float4* q4 = (float4*)out_qst  + (size_t)b * 14400;
        const int lane = tid & 31;
        const int wid  = tid >> 5;
        const int q    = lane & 15;
        const int jh   = lane >> 4;
        for (int i = wid; i < 30; i += 8) {
            float4 ev = enc4[i * 16 + q];
            float4 cv = cb4[codes_s[i] * 16 + q];
            float4* fb = f4 + i * 480 + jh * 16 + q;
            float4* qb = q4 + i * 480 + jh * 16 + q;
            #pragma unroll
            for (int j = 0; j < 30; j += 2) {
                __stcs(fb + j * 16, ev);
                __stcs(qb + j * 16, cv);
            }
        }
    }
    __syncthreads();

    // ================= DECODER init =================
    if (tid < 64) {
        G1[tid * 36]      = 0.f;
        G1[tid * 36 + 33] = 0.f;
        G2[tid * 68]      = 0.f;
        G2[tid * 68 + 65] = 0.f;
    }
    // stage convT2 chunk0 (272 f4) into buf0+buf1 head
    {
        const float4* sp = (const float4*)(g_wt + GW_DW2T);
        ((float4*)WT)[tid] = __ldg(&sp[tid]);
        if (tid < 16) ((float4*)WT)[256 + tid] = __ldg(&sp[256 + tid]);
    }
    __syncthreads();

    // convT1 via M1 table (direct __ldg, stride 64):
    // G1[o][p+1] = relu(db1[o] + sum_k M1[k][code(p-k)][o]).  4o x 4p, 128 act
    if (tid < 128) {
        const int o0 = (tid & 15) * 4;
        const int p0 = (tid >> 4) * 4;
        u64 a01[4], a23[4];
        {
            u64 bb01 = pk2(__ldg(&db1[o0]), __ldg(&db1[o0 + 1]));
            u64 bb23 = pk2(__ldg(&db1[o0 + 2]), __ldg(&db1[o0 + 3]));
            #pragma unroll
            for (int t = 0; t < 4; t++) { a01[t] = bb01; a23[t] = bb23; }
        }
        #pragma unroll
        for (int k = 0; k < 3; k++) {
            #pragma unroll
            for (int t = 0; t < 4; t++) {
                int i = p0 + t - k;
                int cd = ((unsigned)i < 30u) ? codes_s[i] : 10;
                const u64* mp = (const u64*)(g_wt + GW_M1 + (k * 11 + cd) * 64 + o0);
                add2(a01[t], __ldg(mp));
                add2(a23[t], __ldg(mp + 1));
            }
        }
        #pragma unroll
        for (int t = 0; t < 4; t++) {
            float2 p01 = upk(a01[t]), p23 = upk(a23[t]);
            G1[(o0 + 0) * 36 + p0 + t + 1] = fmaxf(p01.x, 0.f);
            G1[(o0 + 1) * 36 + p0 + t + 1] = fmaxf(p01.y, 0.f);
            G1[(o0 + 2) * 36 + p0 + t + 1] = fmaxf(p23.x, 0.f);
            G1[(o0 + 3) * 36 + p0 + t + 1] = fmaxf(p23.y, 0.f);
        }
    }
    __syncthreads();

    // convT2: G1 [64][32] s2 p1 k4 -> G2 [64][64], ReLU.
    // 2o x 8t, f32x2, chunks of 4 cl (272 f4); chunk0 spans buf0+head of buf1 (preloaded)
    {
        const int oo = (tid & 31) * 2;
        const int tt0 = (tid >> 5) * 8;
        u64 ap[8];
        {
            u64 bb = pk2(__ldg(&db2[oo]), __ldg(&db2[oo + 1]));
            #pragma unroll
            for (int t = 0; t < 8; t++) ap[t] = bb;
        }
        const float4* wsrc = (const float4*)(g_wt + GW_DW2T);
        // chunk0 occupies WT[0..1088) contiguous (1088 floats = 272 f4) — buffers alternate
        #pragma unroll 1
        for (int ch = 0; ch < 16; ch++) {
            float4 pre[2];
            if (ch < 15) {
                const float4* sp = wsrc + (ch + 1) * 272;
                pre[0] = __ldg(&sp[tid]);
                if (tid < 16) pre[1] = __ldg(&sp[256 + tid]);
            }
            const float* cur = WT + (ch & 1) * 1088;
            for (int cl = 0; cl < 4; cl++) {
                const float* xr = &G1[(ch * 4 + cl) * 36 + (tt0 >> 1)];
                float4 v = *(const float4*)xr;
                float2 v2 = *(const float2*)(xr + 4);
                u64 xp[6];
                xp[0]=pk(v.x); xp[1]=pk(v.y); xp[2]=pk(v.z); xp[3]=pk(v.w);
                xp[4]=pk(v2.x); xp[5]=pk(v2.y);
                const float* wb = &cur[(cl * 4) * 68 + oo];
                u64 w0 = *(const u64*)(wb);
                u64 w1 = *(const u64*)(wb + 68);
                u64 w2 = *(const u64*)(wb + 136);
                u64 w3 = *(const u64*)(wb + 204);
                #pragma unroll
                for (int t = 0; t < 8; t++) {
                    int u1 = ((t + 1) >> 1) + 1;
                    if (t & 1) {
                        fma2(ap[t], w0, xp[u1]);
                        fma2(ap[t], w2, xp[u1 - 1]);
                    } else {
                        fma2(ap[t], w1, xp[u1]);
                        fma2(ap[t], w3, xp[u1 - 1]);
                    }
                }
            }
            if (ch < 15) {
                float4* dp = (float4*)(WT + ((ch + 1) & 1) * 1088);
                dp[tid] = pre[0];
                if (tid < 16) dp[256 + tid] = pre[1];
            }
            __syncthreads();
        }
        // epilogue: store G2 + stage convT3 chunk0 (272 f4)
        #pragma unroll
        for (int t = 0; t < 8; t++) {
            float2 p = upk(ap[t]);
            G2[oo * 68 + tt0 + t + 1]       = fmaxf(p.x, 0.f);
            G2[(oo + 1) * 68 + tt0 + t + 1] = fmaxf(p.y, 0.f);
        }
        {
            const float4* sp = (const float4*)(g_wt + GW_DW3T);
            ((float4*)WT)[tid] = __ldg(&sp[tid]);
            if (tid < 16) ((float4*)WT)[256 + tid] = __ldg(&sp[256 + tid]);
        }
        __syncthreads();
    }

    // convT3: G2 [64][64] s2 p1 k4 -> G3 [32][128] (aliases G1).
    // 2o x 8t, f32x2, chunks of 8 cl (272 f4)
    {
        const int oo = (tid & 15) * 2;
        const int tt0 = (tid >> 4) * 8;
        u64 ap[8];
        {
            u64 bb = pk2(__ldg(&db3[oo]), __ldg(&db3[oo + 1]));
            #pragma unroll
            for (int t = 0; t < 8; t++) ap[t] = bb;
        }
        const float4* wsrc = (const float4*)(g_wt + GW_DW3T);
        #pragma unroll 1
        for (int ch = 0; ch < 8; ch++) {
            float4 pre[2];
            if (ch < 7) {
                const float4* sp = wsrc + (ch + 1) * 272;
                pre[0] = __ldg(&sp[tid]);
                if (tid < 16) pre[1] = __ldg(&sp[256 + tid]);
            }
            const float* cur = WT + (ch & 1) * 1088;
            for (int cl = 0; cl < 8; cl++) {
                const float* xr = &G2[(ch * 8 + cl) * 68 + (tt0 >> 1)];
                float4 v = *(const float4*)xr;
                float2 v2 = *(const float2*)(xr + 4);
                u64 xp[6];
                xp[0]=pk(v.x); xp[1]=pk(v.y); xp[2]=pk(v.z); xp[3]=pk(v.w);
                xp[4]=pk(v2.x); xp[5]=pk(v2.y);
                const float* wb = &cur[(cl * 4) * 34 + oo];
                u64 w0 = *(const u64*)(wb);
                u64 w1 = *(const u64*)(wb + 34);
                u64 w2 = *(const u64*)(wb + 68);
                u64 w3 = *(const u64*)(wb + 102);
                #pragma unroll
                for (int t = 0; t < 8; t++) {
                    int u1 = ((t + 1) >> 1) + 1;
                    if (t & 1) {
                        fma2(ap[t], w0, xp[u1]);
                        fma2(ap[t], w2, xp[u1 - 1]);
                    } else {
                        fma2(ap[t], w1, xp[u1]);
                        fma2(ap[t], w3, xp[u1 - 1]);
                    }
                }
            }
            if (ch < 7) {
                float4* dp = (float4*)(WT + ((ch + 1) & 1) * 1088);
                dp[tid] = pre[0];
                if (tid < 16) dp[256 + tid] = pre[1];
            }
            __syncthreads();
        }
        // epilogue: store G3 (aliases G1)
        #pragma unroll
        for (int t = 0; t < 8; t++) {
            float2 p = upk(ap[t]);
            G3[oo * 132 + tt0 + t]       = p.x;
            G3[(oo + 1) * 132 + tt0 + t] = p.y;
        }
        __syncthreads();
    }

    // final GEMM: logits[l][v] = sum_e G3[e][l] * ow[v*32+e] + ob[v].
    // 4v x 8l x2, f32x2, weights direct __ldg (L1-resident)
    {
        const int v0 = (tid & 31) * 4;
        const int l0 = (tid >> 5) * 16;
        u64 b01 = pk2(__ldg(&ob[v0]), __ldg(&ob[v0 + 1]));
        u64 b23 = pk2(__ldg(&ob[v0 + 2]), __ldg(&ob[v0 + 3]));
        #pragma unroll
        for (int lh = 0; lh < 2; lh++) {
            const int l = l0 + lh * 8;
            u64 g01[8], g23[8];
            #pragma unroll
            for (int u = 0; u < 8; u++) { g01[u] = b01; g23[u] = b23; }
            for (int e = 0; e < 32; e++) {
                const float* xr = &G3[e * 132 + l];
                float4 va = *(const float4*)xr;
                float4 vb = *(const float4*)(xr + 4);
                u64 xp[8];
                xp[0]=pk(va.x); xp[1]=pk(va.y); xp[2]=pk(va.z); xp[3]=pk(va.w);
                xp[4]=pk(vb.x); xp[5]=pk(vb.y); xp[6]=pk(vb.z); xp[7]=pk(vb.w);
                const u64* wp = (const u64*)(g_wt + GW_OWT + e * 132 + v0);
                u64 w01 = __ldg(wp), w23 = __ldg(wp + 1);
                #pragma unroll
                for (int u = 0; u < 8; u++) {
                    fma2(g01[u], w01, xp[u]);
                    fma2(g23[u], w23, xp[u]);
                }
            }
            float* outp = out_logits + ((size_t)b * 128 + l) * 128 + v0;
            #pragma unroll
            for (int u = 0; u < 8; u++) {
                float2 p01 = upk(g01[u]), p23 = upk(g23[u]);
                float4 vv = make_float4(p01.x, p01.y, p23.x, p23.y);
                __stcs((float4*)(outp + (size_t)u * 128), vv);
            }
        }
    }
}

// Deterministic loss reduce
__global__ void loss_kernel(float* __restrict__ out_loss)
{
    __shared__ float sm[256];
    float a = 0.f;
    for (int i = threadIdx.x; i < BB; i += 256) a += g_partial[i];
    sm[threadIdx.x] = a;
    __syncthreads();
    for (int sft = 128; sft > 0; sft >>= 1) {
        if (threadIdx.x < sft) sm[threadIdx.x] += sm[threadIdx.x + sft];
        __syncthreads();
    }
    if (threadIdx.x == 0)
        out_loss[0] = sm[0] * (1.25f / (2048.f * 30.f * 64.f));
}

extern "C" void kernel_launch(void* const* d_in, const int* in_sizes, int n_in,
                              void* d_out, int out_size)
{
    const int*   ti     = (const int*)  d_in[0];
    const float* emb    = (const float*)d_in[1];
    const float* enc_w1 = (const float*)d_in[2];
    const float* enc_b1 = (const float*)d_in[3];
    const float* enc_w2 = (const float*)d_in[4];
    const float* enc_b2 = (const float*)d_in[5];
    const float* enc_w3 = (const float*)d_in[6];
    const float* enc_b3 = (const float*)d_in[7];
    const float* cb     = (const float*)d_in[8];
    const float* dec_w1 = (const float*)d_in[9];
    const float* dec_b1 = (const float*)d_in[10];
    const float* dec_w2 = (const float*)d_in[11];
    const float* dec_b2 = (const float*)d_in[12];
    const float* dec_w3 = (const float*)d_in[13];
    const float* dec_b3 = (const float*)d_in[14];
    const float* out_w  = (const float*)d_in[15];
    const float* out_b  = (const float*)d_in[16];

    float* out        = (float*)d_out;
    float* out_logits = out;
    float* out_puzz   = out + OFF_PUZZ;
    float* out_feat   = out + OFF_FEAT;
    float* out_qst    = out + OFF_QST;
    float* out_loss   = out + OFF_LOSS;

    cudaFuncSetAttribute(fused_kernel, cudaFuncAttributeMaxDynamicSharedMemorySize, SM_BYTES);
    cudaFuncSetAttribute(fused_kernel, cudaFuncAttributePreferredSharedMemoryCarveout, 86);

    prep_kernel<<<512, 256>>>(enc_w1, enc_w2, enc_w3, dec_w1, dec_w2, dec_w3, out_w, emb, cb);
    fused_kernel<<<BB, 256, SM_BYTES>>>(ti, enc_b1, enc_b2, enc_b3, cb,
                                        dec_b1, dec_b2, dec_b3, out_b,
                                        out_logits, out_feat, out_qst, out_puzz);
    loss_kernel<<<1, 256>>>(out_loss);
}